// round 1
// baseline (speedup 1.0000x reference)
#include <cuda_runtime.h>
#include <math.h>

#define SEQ 2048
#define DIM 4096
#define NH 32
#define HD 128
#define HID 11008

// ---------------- scratch (no cudaMalloc allowed) ----------------
__device__ float g_xn[SEQ * DIM];      // xn, later hn
__device__ float g_q[SEQ * DIM];
__device__ float g_k[SEQ * DIM];
__device__ float g_v[SEQ * DIM];
__device__ float g_attn[SEQ * DIM];
__device__ float g_h[SEQ * DIM];
__device__ float g_g1[SEQ * HID];
__device__ float g_g3[SEQ * HID];

// ---------------- RMSNorm: one block per row ----------------
__global__ void rmsnorm_kernel(const float* __restrict__ x,
                               const float* __restrict__ w,
                               float* __restrict__ o) {
    int row = blockIdx.x;
    int tid = threadIdx.x;
    const float4* xr = (const float4*)(x + (size_t)row * DIM);
    __shared__ float red[8];

    float4 vals[4];
    float ss = 0.f;
#pragma unroll
    for (int i = 0; i < 4; i++) {
        float4 v = xr[tid + i * 256];
        vals[i] = v;
        ss += v.x * v.x + v.y * v.y + v.z * v.z + v.w * v.w;
    }
#pragma unroll
    for (int off = 16; off; off >>= 1) ss += __shfl_xor_sync(~0u, ss, off);
    if ((tid & 31) == 0) red[tid >> 5] = ss;
    __syncthreads();
    float tot = 0.f;
#pragma unroll
    for (int i = 0; i < 8; i++) tot += red[i];
    float rs = rsqrtf(tot * (1.0f / DIM) + 1e-5f);

    const float4* wr = (const float4*)w;
    float4* orow = (float4*)(o + (size_t)row * DIM);
#pragma unroll
    for (int i = 0; i < 4; i++) {
        float4 v = vals[i];
        float4 wv = wr[tid + i * 256];
        v.x *= rs * wv.x; v.y *= rs * wv.y; v.z *= rs * wv.z; v.w *= rs * wv.w;
        orow[tid + i * 256] = v;
    }
}

// ---------------- SGEMM NT: C[M,N] = A[M,K] * B[N,K]^T (+R) ----------------
// BM=BN=128, BK=8, 256 threads, 8x8 per thread
template <int RES>
__global__ void __launch_bounds__(256) sgemm_nt(const float* __restrict__ A,
                                                const float* __restrict__ B,
                                                const float* __restrict__ R,
                                                float* __restrict__ C,
                                                int M, int N, int K) {
    __shared__ float As[8][128];
    __shared__ float Bs[8][128];
    int tid = threadIdx.x;
    int tx = tid & 15, ty = tid >> 4;
    int bn = blockIdx.x, bm = blockIdx.y;

    int lrow = tid >> 1;         // 0..127
    int lcol = (tid & 1) << 2;   // 0 or 4
    const float* Ap = A + (size_t)(bm * 128 + lrow) * K + lcol;
    const float* Bp = B + (size_t)(bn * 128 + lrow) * K + lcol;

    float acc[8][8];
#pragma unroll
    for (int i = 0; i < 8; i++)
#pragma unroll
        for (int j = 0; j < 8; j++) acc[i][j] = 0.f;

    for (int k0 = 0; k0 < K; k0 += 8) {
        float4 av = *(const float4*)(Ap + k0);
        float4 bv = *(const float4*)(Bp + k0);
        As[lcol + 0][lrow] = av.x; As[lcol + 1][lrow] = av.y;
        As[lcol + 2][lrow] = av.z; As[lcol + 3][lrow] = av.w;
        Bs[lcol + 0][lrow] = bv.x; Bs[lcol + 1][lrow] = bv.y;
        Bs[lcol + 2][lrow] = bv.z; Bs[lcol + 3][lrow] = bv.w;
        __syncthreads();
#pragma unroll
        for (int kk = 0; kk < 8; kk++) {
            float a[8], b[8];
#pragma unroll
            for (int i = 0; i < 8; i++) a[i] = As[kk][ty * 8 + i];
#pragma unroll
            for (int j = 0; j < 8; j++) b[j] = Bs[kk][tx * 8 + j];
#pragma unroll
            for (int i = 0; i < 8; i++)
#pragma unroll
                for (int j = 0; j < 8; j++) acc[i][j] = fmaf(a[i], b[j], acc[i][j]);
        }
        __syncthreads();
    }

#pragma unroll
    for (int i = 0; i < 8; i++) {
        int row = bm * 128 + ty * 8 + i;
        float* Cr = C + (size_t)row * N + bn * 128 + tx * 8;
        const float* Rr = RES ? (R + (size_t)row * N + bn * 128 + tx * 8) : nullptr;
#pragma unroll
        for (int j = 0; j < 8; j++) {
            float val = acc[i][j];
            if (RES) val += Rr[j];
            Cr[j] = val;
        }
    }
}

// ---------------- RoPE: interleaved pairs, applied to q and k ----------------
__global__ void rotary_kernel(float* __restrict__ q, float* __restrict__ k,
                              const float* __restrict__ cosb,
                              const float* __restrict__ sinb) {
    float* t = blockIdx.y ? k : q;
    int idx = blockIdx.x * 256 + threadIdx.x;  // < SEQ * NH * 64
    int s = idx >> 11;            // NH*64 = 2048 pairs per row
    int rem = idx & 2047;
    int i = rem & 63;
    int h = rem >> 6;
    float c = cosb[s * 64 + i];
    float sn = sinb[s * 64 + i];
    size_t base = (size_t)s * DIM + h * HD + 2 * i;
    float x0 = t[base], x1 = t[base + 1];
    t[base]     = x0 * c - x1 * sn;
    t[base + 1] = x0 * sn + x1 * c;
}

// ---------------- causal attention: warp per q-row, online softmax ----------
__global__ void __launch_bounds__(256) attn_kernel(const float* __restrict__ Q,
                                                   const float* __restrict__ K,
                                                   const float* __restrict__ V,
                                                   float* __restrict__ O) {
    __shared__ float ks[32][128];
    __shared__ float vs[32][128];
    int h = blockIdx.y;
    int qt = blockIdx.x;          // 8 q-rows per block
    int tid = threadIdx.x;
    int warp = tid >> 5, lane = tid & 31;
    int qrow = qt * 8 + warp;

    float4 qv = *(const float4*)(Q + (size_t)qrow * DIM + h * HD + lane * 4);
    float m = -1e30f, l = 0.f;
    float4 acc = {0.f, 0.f, 0.f, 0.f};
    int qmax = qt * 8 + 7;
    int nkb = qmax / 32 + 1;
    const float scale = 0.08838834764831845f;  // 1/sqrt(128)

    for (int kb = 0; kb < nkb; kb++) {
        __syncthreads();
#pragma unroll
        for (int i = 0; i < 4; i++) {
            int li = tid + i * 256;   // 0..1023 float4 slots
            int rr = li >> 5;
            int c4 = li & 31;
            size_t gaddr = (size_t)(kb * 32 + rr) * DIM + h * HD;
            ((float4*)ks[rr])[c4] = ((const float4*)(K + gaddr))[c4];
            ((float4*)vs[rr])[c4] = ((const float4*)(V + gaddr))[c4];
        }
        __syncthreads();
        int jend = min(31, qrow - kb * 32);
        for (int j = 0; j <= jend; j++) {
            float4 kv = ((const float4*)ks[j])[lane];
            float s = qv.x * kv.x + qv.y * kv.y + qv.z * kv.z + qv.w * kv.w;
#pragma unroll
            for (int off = 16; off; off >>= 1) s += __shfl_xor_sync(~0u, s, off);
            s *= scale;
            float4 vv = ((const float4*)vs[j])[lane];
            if (s > m) {
                float c = __expf(m - s);  // m=-1e30 first time -> c=0
                l = l * c + 1.f;
                acc.x = acc.x * c + vv.x;
                acc.y = acc.y * c + vv.y;
                acc.z = acc.z * c + vv.z;
                acc.w = acc.w * c + vv.w;
                m = s;
            } else {
                float p = __expf(s - m);
                l += p;
                acc.x += p * vv.x; acc.y += p * vv.y;
                acc.z += p * vv.z; acc.w += p * vv.w;
            }
        }
    }
    float inv = 1.f / l;
    float4 o;
    o.x = acc.x * inv; o.y = acc.y * inv; o.z = acc.z * inv; o.w = acc.w * inv;
    *(float4*)(O + (size_t)qrow * DIM + h * HD + lane * 4) = o;
}

// ---------------- SwiGLU elementwise: g1 = silu(g1) * g3 ----------------
__global__ void swiglu_kernel(float* __restrict__ g1, const float* __restrict__ g3,
                              int n) {
    int i = blockIdx.x * 256 + threadIdx.x;
    if (i < n) {
        float a = g1[i];
        float sig = 1.f / (1.f + __expf(-a));
        g1[i] = a * sig * g3[i];
    }
}

// ---------------- launch ----------------
extern "C" void kernel_launch(void* const* d_in, const int* in_sizes, int n_in,
                              void* d_out, int out_size) {
    const float* x   = (const float*)d_in[0];
    const float* fc  = (const float*)d_in[1];
    const float* fs  = (const float*)d_in[2];
    /* d_in[3] = mask (implied by causal loop) */
    const float* anw = (const float*)d_in[4];
    const float* wq  = (const float*)d_in[5];
    const float* wk  = (const float*)d_in[6];
    const float* wv  = (const float*)d_in[7];
    const float* wo  = (const float*)d_in[8];
    const float* fnw = (const float*)d_in[9];
    const float* w1  = (const float*)d_in[10];
    const float* w2  = (const float*)d_in[11];
    const float* w3  = (const float*)d_in[12];
    float* out = (float*)d_out;

    float *xn, *q, *k, *v, *attn, *h, *g1, *g3;
    cudaGetSymbolAddress((void**)&xn,   g_xn);
    cudaGetSymbolAddress((void**)&q,    g_q);
    cudaGetSymbolAddress((void**)&k,    g_k);
    cudaGetSymbolAddress((void**)&v,    g_v);
    cudaGetSymbolAddress((void**)&attn, g_attn);
    cudaGetSymbolAddress((void**)&h,    g_h);
    cudaGetSymbolAddress((void**)&g1,   g_g1);
    cudaGetSymbolAddress((void**)&g3,   g_g3);

    dim3 gdd(DIM / 128, SEQ / 128);   // 32 x 16
    dim3 ghd(HID / 128, SEQ / 128);   // 86 x 16

    // xn = rmsnorm(x)
    rmsnorm_kernel<<<SEQ, 256>>>(x, anw, xn);
    // q,k,v = xn @ W^T
    sgemm_nt<0><<<gdd, 256>>>(xn, wq, nullptr, q, SEQ, DIM, DIM);
    sgemm_nt<0><<<gdd, 256>>>(xn, wk, nullptr, k, SEQ, DIM, DIM);
    sgemm_nt<0><<<gdd, 256>>>(xn, wv, nullptr, v, SEQ, DIM, DIM);
    // RoPE on q and k
    rotary_kernel<<<dim3(SEQ * NH * 64 / 256, 2), 256>>>(q, k, fc, fs);
    // causal attention
    attn_kernel<<<dim3(SEQ / 8, NH), 256>>>(q, k, v, attn);
    // h = x + attn @ wo^T
    sgemm_nt<1><<<gdd, 256>>>(attn, wo, x, h, SEQ, DIM, DIM);
    // hn = rmsnorm(h)  (reuse xn buffer)
    rmsnorm_kernel<<<SEQ, 256>>>(h, fnw, xn);
    // g1 = hn @ w1^T ; g3 = hn @ w3^T
    sgemm_nt<0><<<ghd, 256>>>(xn, w1, nullptr, g1, SEQ, HID, DIM);
    sgemm_nt<0><<<ghd, 256>>>(xn, w3, nullptr, g3, SEQ, HID, DIM);
    // g1 = silu(g1) * g3
    swiglu_kernel<<<(SEQ * HID + 255) / 256, 256>>>(g1, g3, SEQ * HID);
    // out = h + g1 @ w2^T
    sgemm_nt<1><<<gdd, 256>>>(g1, w2, h, out, SEQ, DIM, HID);
}

// round 3
// speedup vs baseline: 1.5127x; 1.5127x over previous
#include <cuda_runtime.h>
#include <cuda_bf16.h>
#include <cstdint>
#include <math.h>

#define SEQ 2048
#define DIM 4096
#define NH 32
#define HD 128
#define HID 11008

// ---------------- scratch (no cudaMalloc allowed) ----------------
__device__ float g_xn[SEQ * DIM];
__device__ float g_q[SEQ * DIM];
__device__ float g_k[SEQ * DIM];
__device__ float g_v[SEQ * DIM];
__device__ float g_attn[SEQ * DIM];
__device__ float g_h[SEQ * DIM];
__device__ float g_g1[SEQ * HID];
__device__ float g_g3[SEQ * HID];

__device__ __forceinline__ uint32_t smem_u32(const void* p) {
    uint32_t a;
    asm("{ .reg .u64 t; cvta.to.shared.u64 t, %1; cvt.u32.u64 %0, t; }"
        : "=r"(a) : "l"(p));
    return a;
}

#define LDSM_X4(r, addr)                                                      \
    asm volatile("ldmatrix.sync.aligned.m8n8.x4.shared.b16 {%0,%1,%2,%3}, [%4];" \
                 : "=r"((r)[0]), "=r"((r)[1]), "=r"((r)[2]), "=r"((r)[3])     \
                 : "r"(addr))

#define MMA_BF16(d, a, b0, b1)                                                \
    asm volatile(                                                             \
        "mma.sync.aligned.m16n8k16.row.col.f32.bf16.bf16.f32 "                \
        "{%0,%1,%2,%3},{%4,%5,%6,%7},{%8,%9},{%0,%1,%2,%3};"                  \
        : "+f"((d)[0]), "+f"((d)[1]), "+f"((d)[2]), "+f"((d)[3])              \
        : "r"((a)[0]), "r"((a)[1]), "r"((a)[2]), "r"((a)[3]), "r"(b0), "r"(b1))

// fp32 -> bf16 hi + lo residual
__device__ __forceinline__ void cvt2(float x0, float x1, uint32_t& h, uint32_t& l) {
    __nv_bfloat16 h0 = __float2bfloat16_rn(x0);
    __nv_bfloat16 h1 = __float2bfloat16_rn(x1);
    float r0 = x0 - __bfloat162float(h0);
    float r1 = x1 - __bfloat162float(h1);
    __nv_bfloat162 hh(h0, h1);
    __nv_bfloat162 ll(__float2bfloat16_rn(r0), __float2bfloat16_rn(r1));
    h = *(uint32_t*)&hh;
    l = *(uint32_t*)&ll;
}
__device__ __forceinline__ void cvt8(float4 v0, float4 v1, uint4& h, uint4& l) {
    cvt2(v0.x, v0.y, h.x, l.x);
    cvt2(v0.z, v0.w, h.y, l.y);
    cvt2(v1.x, v1.y, h.z, l.z);
    cvt2(v1.z, v1.w, h.w, l.w);
}

// smem swizzle: element row r (64B/row of bf16x32), 16B chunk base cb
__device__ __forceinline__ uint32_t swz(int r, uint32_t cb) {
    return (uint32_t)r * 64 + (cb ^ (((r >> 1) & 3) << 4));
}

// ============ GEMM: C[M,N] = A[M,K] * B[N,K]^T (+R), bf16-split x3 ==========
// BM=BN=128, BK=32, 256 threads, warp grid 2(M) x 4(N), warp tile 64x32
// smem per stage 32KB: AHI 0 | ALO 8K | BHI 16K | BLO 24K ; double buffered
#define GEMM_SMEM 65536

template <int RES>
__global__ void __launch_bounds__(256, 1) gemm_mma(const float* __restrict__ A,
                                                   const float* __restrict__ B,
                                                   const float* __restrict__ R,
                                                   float* __restrict__ C,
                                                   int M, int N, int K) {
    extern __shared__ __align__(1024) char smem[];
    uint32_t sbase = smem_u32(smem);
    int tid = threadIdx.x;
    int lane = tid & 31, wid = tid >> 5;
    int wm = (wid >> 2) * 64;
    int wn = (wid & 3) * 32;
    int bm = blockIdx.y, bn = blockIdx.x;

    const float* Abase = A + (size_t)(bm * 128) * K;
    const float* Bbase = B + (size_t)(bn * 128) * K;
    int NS = K / 32;

    float4 pf[8];

#define LDG_STAGE(s)                                                          \
    {                                                                         \
        int k0 = (s) * 32;                                                    \
        _Pragma("unroll") for (int it = 0; it < 4; it++) {                    \
            const float* base = (it < 2) ? Abase : Bbase;                     \
            int id = tid + (it & 1) * 256;                                    \
            int row = id >> 2, cc = id & 3;                                   \
            const float4* g = (const float4*)(base + (size_t)row * K + k0 + cc * 8); \
            pf[it * 2] = __ldg(g);                                            \
            pf[it * 2 + 1] = __ldg(g + 1);                                    \
        }                                                                     \
    }

#define STS_STAGE(buf)                                                        \
    {                                                                         \
        char* st = smem + (buf) * 32768;                                      \
        _Pragma("unroll") for (int it = 0; it < 4; it++) {                    \
            int id = tid + (it & 1) * 256;                                    \
            int row = id >> 2, cc = id & 3;                                   \
            uint4 h, l;                                                       \
            cvt8(pf[it * 2], pf[it * 2 + 1], h, l);                           \
            uint32_t off = swz(row, (uint32_t)cc << 4);                       \
            int hb = (it < 2) ? 0 : 16384;                                    \
            *(uint4*)(st + hb + off) = h;                                     \
            *(uint4*)(st + hb + 8192 + off) = l;                              \
        }                                                                     \
    }

    float acc[4][4][4];
#pragma unroll
    for (int i = 0; i < 4; i++)
#pragma unroll
        for (int j = 0; j < 4; j++)
#pragma unroll
            for (int t = 0; t < 4; t++) acc[i][j][t] = 0.f;

    LDG_STAGE(0);
    STS_STAGE(0);
    __syncthreads();

    for (int s = 0; s < NS; s++) {
        int buf = s & 1;
        if (s + 1 < NS) LDG_STAGE(s + 1);
        uint32_t sb = sbase + buf * 32768;
        int sub = lane >> 3;
#pragma unroll
        for (int ks = 0; ks < 2; ks++) {
            uint32_t ah[4][4], al[4][4];
            uint32_t bh[8], bl[8];
#pragma unroll
            for (int mi = 0; mi < 4; mi++) {
                int r = wm + mi * 16 + (lane & 7) + (sub & 1) * 8;
                uint32_t cb = (uint32_t)(ks * 2 + (sub >> 1)) << 4;
                uint32_t off = swz(r, cb);
                LDSM_X4(ah[mi], sb + off);
                LDSM_X4(al[mi], sb + 8192 + off);
            }
#pragma unroll
            for (int np = 0; np < 2; np++) {
                int n = wn + np * 16 + (sub >> 1) * 8 + (lane & 7);
                uint32_t cb = (uint32_t)(ks * 2 + (sub & 1)) << 4;
                uint32_t off = swz(n, cb);
                LDSM_X4(&bh[np * 4], sb + 16384 + off);
                LDSM_X4(&bl[np * 4], sb + 24576 + off);
            }
            // pass 1: Ahi * Bhi
#pragma unroll
            for (int mi = 0; mi < 4; mi++)
#pragma unroll
                for (int ni = 0; ni < 4; ni++) {
                    uint32_t* bp = &bh[(ni >> 1) * 4 + (ni & 1) * 2];
                    MMA_BF16(acc[mi][ni], ah[mi], bp[0], bp[1]);
                }
            // pass 2: Ahi * Blo
#pragma unroll
            for (int mi = 0; mi < 4; mi++)
#pragma unroll
                for (int ni = 0; ni < 4; ni++) {
                    uint32_t* bp = &bl[(ni >> 1) * 4 + (ni & 1) * 2];
                    MMA_BF16(acc[mi][ni], ah[mi], bp[0], bp[1]);
                }
            // pass 3: Alo * Bhi
#pragma unroll
            for (int mi = 0; mi < 4; mi++)
#pragma unroll
                for (int ni = 0; ni < 4; ni++) {
                    uint32_t* bp = &bh[(ni >> 1) * 4 + (ni & 1) * 2];
                    MMA_BF16(acc[mi][ni], al[mi], bp[0], bp[1]);
                }
        }
        if (s + 1 < NS) STS_STAGE((s + 1) & 1);
        __syncthreads();
    }

#pragma unroll
    for (int mi = 0; mi < 4; mi++)
#pragma unroll
        for (int ni = 0; ni < 4; ni++) {
            int r0 = bm * 128 + wm + mi * 16 + (lane >> 2);
            int col = bn * 128 + wn + ni * 8 + (lane & 3) * 2;
            float* p0 = C + (size_t)r0 * N + col;
            float* p1 = p0 + 8 * (size_t)N;
            float2 v0 = {acc[mi][ni][0], acc[mi][ni][1]};
            float2 v1 = {acc[mi][ni][2], acc[mi][ni][3]};
            if (RES) {
                const float* q0 = R + (size_t)r0 * N + col;
                const float* q1 = q0 + 8 * (size_t)N;
                v0.x += q0[0]; v0.y += q0[1];
                v1.x += q1[0]; v1.y += q1[1];
            }
            *(float2*)p0 = v0;
            *(float2*)p1 = v1;
        }
#undef LDG_STAGE
#undef STS_STAGE
}

// ---------------- RMSNorm ----------------
__global__ void rmsnorm_kernel(const float* __restrict__ x,
                               const float* __restrict__ w,
                               float* __restrict__ o) {
    int row = blockIdx.x;
    int tid = threadIdx.x;
    const float4* xr = (const float4*)(x + (size_t)row * DIM);
    __shared__ float red[8];
    float4 vals[4];
    float ss = 0.f;
#pragma unroll
    for (int i = 0; i < 4; i++) {
        float4 v = xr[tid + i * 256];
        vals[i] = v;
        ss += v.x * v.x + v.y * v.y + v.z * v.z + v.w * v.w;
    }
#pragma unroll
    for (int off = 16; off; off >>= 1) ss += __shfl_xor_sync(~0u, ss, off);
    if ((tid & 31) == 0) red[tid >> 5] = ss;
    __syncthreads();
    float tot = 0.f;
#pragma unroll
    for (int i = 0; i < 8; i++) tot += red[i];
    float rs = rsqrtf(tot * (1.0f / DIM) + 1e-5f);
    const float4* wr = (const float4*)w;
    float4* orow = (float4*)(o + (size_t)row * DIM);
#pragma unroll
    for (int i = 0; i < 4; i++) {
        float4 v = vals[i];
        float4 wv = wr[tid + i * 256];
        v.x *= rs * wv.x; v.y *= rs * wv.y; v.z *= rs * wv.z; v.w *= rs * wv.w;
        orow[tid + i * 256] = v;
    }
}

// ---------------- RoPE ----------------
__global__ void rotary_kernel(float* __restrict__ q, float* __restrict__ k,
                              const float* __restrict__ cosb,
                              const float* __restrict__ sinb) {
    float* t = blockIdx.y ? k : q;
    int idx = blockIdx.x * 256 + threadIdx.x;
    int s = idx >> 11;
    int rem = idx & 2047;
    int i = rem & 63;
    int h = rem >> 6;
    float c = cosb[s * 64 + i];
    float sn = sinb[s * 64 + i];
    size_t base = (size_t)s * DIM + h * HD + 2 * i;
    float x0 = t[base], x1 = t[base + 1];
    t[base] = x0 * c - x1 * sn;
    t[base + 1] = x0 * sn + x1 * c;
}

// ---------------- causal attention: warp per q-row ----------------
__global__ void __launch_bounds__(256) attn_kernel(const float* __restrict__ Q,
                                                   const float* __restrict__ K,
                                                   const float* __restrict__ V,
                                                   float* __restrict__ O) {
    __shared__ float ks[32][128];
    __shared__ float vs[32][128];
    int h = blockIdx.y;
    int qt = blockIdx.x;
    int tid = threadIdx.x;
    int warp = tid >> 5, lane = tid & 31;
    int qrow = qt * 8 + warp;

    float4 qv = *(const float4*)(Q + (size_t)qrow * DIM + h * HD + lane * 4);
    float m = -1e30f, l = 0.f;
    float4 acc = {0.f, 0.f, 0.f, 0.f};
    int qmax = qt * 8 + 7;
    int nkb = qmax / 32 + 1;
    const float scale = 0.08838834764831845f;

    for (int kb = 0; kb < nkb; kb++) {
        __syncthreads();
#pragma unroll
        for (int i = 0; i < 4; i++) {
            int li = tid + i * 256;
            int rr = li >> 5;
            int c4 = li & 31;
            size_t gaddr = (size_t)(kb * 32 + rr) * DIM + h * HD;
            ((float4*)ks[rr])[c4] = ((const float4*)(K + gaddr))[c4];
            ((float4*)vs[rr])[c4] = ((const float4*)(V + gaddr))[c4];
        }
        __syncthreads();
        int jend = min(31, qrow - kb * 32);
        for (int j = 0; j <= jend; j++) {
            float4 kv = ((const float4*)ks[j])[lane];
            float s = qv.x * kv.x + qv.y * kv.y + qv.z * kv.z + qv.w * kv.w;
#pragma unroll
            for (int off = 16; off; off >>= 1) s += __shfl_xor_sync(~0u, s, off);
            s *= scale;
            float4 vv = ((const float4*)vs[j])[lane];
            if (s > m) {
                float c = __expf(m - s);
                l = l * c + 1.f;
                acc.x = acc.x * c + vv.x;
                acc.y = acc.y * c + vv.y;
                acc.z = acc.z * c + vv.z;
                acc.w = acc.w * c + vv.w;
                m = s;
            } else {
                float p = __expf(s - m);
                l += p;
                acc.x += p * vv.x; acc.y += p * vv.y;
                acc.z += p * vv.z; acc.w += p * vv.w;
            }
        }
    }
    float inv = 1.f / l;
    float4 o;
    o.x = acc.x * inv; o.y = acc.y * inv; o.z = acc.z * inv; o.w = acc.w * inv;
    *(float4*)(O + (size_t)qrow * DIM + h * HD + lane * 4) = o;
}

// ---------------- SwiGLU ----------------
__global__ void swiglu_kernel(float* __restrict__ g1, const float* __restrict__ g3,
                              int n) {
    int i = blockIdx.x * 256 + threadIdx.x;
    if (i < n) {
        float a = g1[i];
        float sig = 1.f / (1.f + __expf(-a));
        g1[i] = a * sig * g3[i];
    }
}

// ---------------- launch ----------------
extern "C" void kernel_launch(void* const* d_in, const int* in_sizes, int n_in,
                              void* d_out, int out_size) {
    const float* x   = (const float*)d_in[0];
    const float* fc  = (const float*)d_in[1];
    const float* fs  = (const float*)d_in[2];
    const float* anw = (const float*)d_in[4];
    const float* wq  = (const float*)d_in[5];
    const float* wk  = (const float*)d_in[6];
    const float* wv  = (const float*)d_in[7];
    const float* wo  = (const float*)d_in[8];
    const float* fnw = (const float*)d_in[9];
    const float* w1  = (const float*)d_in[10];
    const float* w2  = (const float*)d_in[11];
    const float* w3  = (const float*)d_in[12];
    float* out = (float*)d_out;

    float *xn, *q, *k, *v, *attn, *h, *g1, *g3;
    cudaGetSymbolAddress((void**)&xn,   g_xn);
    cudaGetSymbolAddress((void**)&q,    g_q);
    cudaGetSymbolAddress((void**)&k,    g_k);
    cudaGetSymbolAddress((void**)&v,    g_v);
    cudaGetSymbolAddress((void**)&attn, g_attn);
    cudaGetSymbolAddress((void**)&h,    g_h);
    cudaGetSymbolAddress((void**)&g1,   g_g1);
    cudaGetSymbolAddress((void**)&g3,   g_g3);

    cudaFuncSetAttribute(gemm_mma<0>, cudaFuncAttributeMaxDynamicSharedMemorySize, GEMM_SMEM);
    cudaFuncSetAttribute(gemm_mma<1>, cudaFuncAttributeMaxDynamicSharedMemorySize, GEMM_SMEM);

    dim3 gdd(DIM / 128, SEQ / 128);   // 32 x 16
    dim3 ghd(HID / 128, SEQ / 128);   // 86 x 16

    rmsnorm_kernel<<<SEQ, 256>>>(x, anw, xn);
    gemm_mma<0><<<gdd, 256, GEMM_SMEM>>>(xn, wq, nullptr, q, SEQ, DIM, DIM);
    gemm_mma<0><<<gdd, 256, GEMM_SMEM>>>(xn, wk, nullptr, k, SEQ, DIM, DIM);
    gemm_mma<0><<<gdd, 256, GEMM_SMEM>>>(xn, wv, nullptr, v, SEQ, DIM, DIM);
    rotary_kernel<<<dim3(SEQ * NH * 64 / 256, 2), 256>>>(q, k, fc, fs);
    attn_kernel<<<dim3(SEQ / 8, NH), 256>>>(q, k, v, attn);
    gemm_mma<1><<<gdd, 256, GEMM_SMEM>>>(attn, wo, x, h, SEQ, DIM, DIM);
    rmsnorm_kernel<<<SEQ, 256>>>(h, fnw, xn);
    gemm_mma<0><<<ghd, 256, GEMM_SMEM>>>(xn, w1, nullptr, g1, SEQ, HID, DIM);
    gemm_mma<0><<<ghd, 256, GEMM_SMEM>>>(xn, w3, nullptr, g3, SEQ, HID, DIM);
    swiglu_kernel<<<(SEQ * HID + 255) / 256, 256>>>(g1, g3, SEQ * HID);
    gemm_mma<1><<<gdd, 256, GEMM_SMEM>>>(g1, w2, h, out, SEQ, DIM, HID);
}

// round 8
// speedup vs baseline: 2.6480x; 1.7505x over previous
#include <cuda_runtime.h>
#include <cuda_bf16.h>
#include <cstdint>
#include <math.h>

#define SEQ 2048
#define DIM 4096
#define NH 32
#define HD 128
#define HID 11008

// ---------------- scratch (no cudaMalloc allowed) ----------------
__device__ float g_q[SEQ * DIM];
__device__ float g_k[SEQ * DIM];
__device__ float g_v[SEQ * DIM];
__device__ float g_h[SEQ * DIM];
__device__ float g_g1[SEQ * HID];
__device__ float g_g3[SEQ * HID];

__device__ __nv_bfloat16 g_xnh[SEQ * DIM], g_xnl[SEQ * DIM];
__device__ __nv_bfloat16 g_ath[SEQ * DIM], g_atl[SEQ * DIM];
__device__ __nv_bfloat16 g_gh[SEQ * HID],  g_gl[SEQ * HID];

__device__ __nv_bfloat16 g_wqh[DIM * DIM], g_wql[DIM * DIM];
__device__ __nv_bfloat16 g_wkh[DIM * DIM], g_wkl[DIM * DIM];
__device__ __nv_bfloat16 g_wvh[DIM * DIM], g_wvl[DIM * DIM];
__device__ __nv_bfloat16 g_woh[DIM * DIM], g_wol[DIM * DIM];
__device__ __nv_bfloat16 g_w1h[HID * DIM], g_w1l[HID * DIM];
__device__ __nv_bfloat16 g_w3h[HID * DIM], g_w3l[HID * DIM];
__device__ __nv_bfloat16 g_w2h[DIM * HID], g_w2l[DIM * HID];

__device__ __forceinline__ uint32_t smem_u32(const void* p) {
    uint32_t a;
    asm("{ .reg .u64 t; cvta.to.shared.u64 t, %1; cvt.u32.u64 %0, t; }"
        : "=r"(a) : "l"(p));
    return a;
}

#define LDSM_X4(r, addr)                                                      \
    asm volatile("ldmatrix.sync.aligned.m8n8.x4.shared.b16 {%0,%1,%2,%3}, [%4];" \
                 : "=r"((r)[0]), "=r"((r)[1]), "=r"((r)[2]), "=r"((r)[3])     \
                 : "r"(addr))

#define MMA_BF16(d, a, b0, b1)                                                \
    asm volatile(                                                             \
        "mma.sync.aligned.m16n8k16.row.col.f32.bf16.bf16.f32 "                \
        "{%0,%1,%2,%3},{%4,%5,%6,%7},{%8,%9},{%0,%1,%2,%3};"                  \
        : "+f"((d)[0]), "+f"((d)[1]), "+f"((d)[2]), "+f"((d)[3])              \
        : "r"((a)[0]), "r"((a)[1]), "r"((a)[2]), "r"((a)[3]), "r"(b0), "r"(b1))

#define CP16(dst, src)                                                        \
    asm volatile("cp.async.cg.shared.global [%0], [%1], 16;"                  \
                 :: "r"(dst), "l"(src))
#define CP_COMMIT() asm volatile("cp.async.commit_group;")
#define CP_WAIT(n)  asm volatile("cp.async.wait_group %0;" :: "n"(n))

// fp32 -> bf16 hi + lo residual (2 elems -> packed bf16x2 words)
__device__ __forceinline__ void cvt2(float x0, float x1, uint32_t& h, uint32_t& l) {
    __nv_bfloat16 h0 = __float2bfloat16_rn(x0);
    __nv_bfloat16 h1 = __float2bfloat16_rn(x1);
    float r0 = x0 - __bfloat162float(h0);
    float r1 = x1 - __bfloat162float(h1);
    __nv_bfloat162 hh(h0, h1);
    __nv_bfloat162 ll(__float2bfloat16_rn(r0), __float2bfloat16_rn(r1));
    h = *(uint32_t*)&hh;
    l = *(uint32_t*)&ll;
}

// smem row = 32 bf16 = 64B, 4 chunks of 16B, XOR-swizzled
__device__ __forceinline__ uint32_t swz(int r, uint32_t cb) {
    return (uint32_t)r * 64 + (cb ^ (((r >> 1) & 3) << 4));
}

// ============ GEMM: C = A * B^T (+R), A/B pre-split bf16 hi/lo ==============
// BM=BN=128, BK=32, 256 threads, warp grid 2x4, warp tile 64x32
// stage 32KB: AH 0 | AL 8K | BH 16K | BL 24K ; 3 stages
#define GEMM_SMEM (3 * 32768)

template <int RES>
__global__ void __launch_bounds__(256, 2) gemm_bf(
    const __nv_bfloat16* __restrict__ Ah, const __nv_bfloat16* __restrict__ Al,
    const __nv_bfloat16* __restrict__ Bh, const __nv_bfloat16* __restrict__ Bl,
    const float* __restrict__ R, float* __restrict__ C, int M, int N, int K) {
    extern __shared__ __align__(1024) char smem[];
    uint32_t sbase = smem_u32(smem);
    int tid = threadIdx.x;
    int lane = tid & 31, wid = tid >> 5;
    int wm = (wid >> 2) * 64;
    int wn = (wid & 3) * 32;
    int bm = blockIdx.y, bn = blockIdx.x;

    const __nv_bfloat16* Ahb = Ah + (size_t)(bm * 128) * K;
    const __nv_bfloat16* Alb = Al + (size_t)(bm * 128) * K;
    const __nv_bfloat16* Bhb = Bh + (size_t)(bn * 128) * K;
    const __nv_bfloat16* Blb = Bl + (size_t)(bn * 128) * K;
    int NS = K / 32;

#define ISSUE(s)                                                              \
    {                                                                         \
        int k0 = (s) * 32;                                                    \
        uint32_t sb = sbase + ((s) % 3) * 32768;                              \
        _Pragma("unroll") for (int it = 0; it < 8; it++) {                    \
            int id = tid + (it & 1) * 256;                                    \
            int row = id >> 2, kc = id & 3;                                   \
            const __nv_bfloat16* src =                                        \
                ((it >> 1) == 0 ? Ahb : (it >> 1) == 1 ? Alb                  \
                 : (it >> 1) == 2 ? Bhb : Blb) +                              \
                (size_t)row * K + k0 + kc * 8;                                \
            uint32_t dst = sb + (uint32_t)(it >> 1) * 8192 +                  \
                           swz(row, (uint32_t)kc << 4);                       \
            CP16(dst, src);                                                   \
        }                                                                     \
        CP_COMMIT();                                                          \
    }

    float acc[4][4][4];
#pragma unroll
    for (int i = 0; i < 4; i++)
#pragma unroll
        for (int j = 0; j < 4; j++)
#pragma unroll
            for (int t = 0; t < 4; t++) acc[i][j][t] = 0.f;

    ISSUE(0);
    ISSUE(1);

    int sub = lane >> 3;
    for (int s = 0; s < NS; s++) {
        CP_WAIT(1);
        __syncthreads();
        if (s + 2 < NS) ISSUE(s + 2);
        uint32_t sb = sbase + (s % 3) * 32768;
#pragma unroll
        for (int ks = 0; ks < 2; ks++) {
            uint32_t bh[8], bl[8];
#pragma unroll
            for (int np = 0; np < 2; np++) {
                int n = wn + np * 16 + (sub >> 1) * 8 + (lane & 7);
                uint32_t cb = (uint32_t)(ks * 2 + (sub & 1)) << 4;
                uint32_t off = swz(n, cb);
                LDSM_X4(&bh[np * 4], sb + 16384 + off);
                LDSM_X4(&bl[np * 4], sb + 24576 + off);
            }
#pragma unroll
            for (int mi = 0; mi < 4; mi++) {
                uint32_t ah[4], al[4];
                int r = wm + mi * 16 + (lane & 7) + (sub & 1) * 8;
                uint32_t cb = (uint32_t)(ks * 2 + (sub >> 1)) << 4;
                uint32_t off = swz(r, cb);
                LDSM_X4(ah, sb + off);
                LDSM_X4(al, sb + 8192 + off);
#pragma unroll
                for (int ni = 0; ni < 4; ni++) {
                    uint32_t* bp = &bh[(ni >> 1) * 4 + (ni & 1) * 2];
                    MMA_BF16(acc[mi][ni], ah, bp[0], bp[1]);
                }
#pragma unroll
                for (int ni = 0; ni < 4; ni++) {
                    uint32_t* bp = &bl[(ni >> 1) * 4 + (ni & 1) * 2];
                    MMA_BF16(acc[mi][ni], ah, bp[0], bp[1]);
                }
#pragma unroll
                for (int ni = 0; ni < 4; ni++) {
                    uint32_t* bp = &bh[(ni >> 1) * 4 + (ni & 1) * 2];
                    MMA_BF16(acc[mi][ni], al, bp[0], bp[1]);
                }
            }
        }
        __syncthreads();
    }

#pragma unroll
    for (int mi = 0; mi < 4; mi++)
#pragma unroll
        for (int ni = 0; ni < 4; ni++) {
            int r0 = bm * 128 + wm + mi * 16 + (lane >> 2);
            int col = bn * 128 + wn + ni * 8 + (lane & 3) * 2;
            float* p0 = C + (size_t)r0 * N + col;
            float* p1 = p0 + 8 * (size_t)N;
            float2 v0 = {acc[mi][ni][0], acc[mi][ni][1]};
            float2 v1 = {acc[mi][ni][2], acc[mi][ni][3]};
            if (RES) {
                const float* q0 = R + (size_t)r0 * N + col;
                const float* q1 = q0 + 8 * (size_t)N;
                v0.x += q0[0]; v0.y += q0[1];
                v1.x += q1[0]; v1.y += q1[1];
            }
            *(float2*)p0 = v0;
            *(float2*)p1 = v1;
        }
#undef ISSUE
}

// ---------------- weight split: fp32 -> bf16 hi/lo ----------------
__global__ void split_kernel(const float* __restrict__ w,
                             __nv_bfloat16* __restrict__ h,
                             __nv_bfloat16* __restrict__ l, int n4) {
    int i = blockIdx.x * 256 + threadIdx.x;
    if (i < n4) {
        float4 v = ((const float4*)w)[i];
        uint32_t h0, l0, h1, l1;
        cvt2(v.x, v.y, h0, l0);
        cvt2(v.z, v.w, h1, l1);
        ((uint2*)h)[i] = make_uint2(h0, h1);
        ((uint2*)l)[i] = make_uint2(l0, l1);
    }
}

// ---------------- RMSNorm -> bf16 hi/lo ----------------
__global__ void rmsnorm_bf(const float* __restrict__ x,
                           const float* __restrict__ w,
                           __nv_bfloat16* __restrict__ oh,
                           __nv_bfloat16* __restrict__ ol) {
    int row = blockIdx.x;
    int tid = threadIdx.x;
    const float4* xr = (const float4*)(x + (size_t)row * DIM);
    __shared__ float red[8];
    float4 vals[4];
    float ss = 0.f;
#pragma unroll
    for (int i = 0; i < 4; i++) {
        float4 v = xr[tid + i * 256];
        vals[i] = v;
        ss += v.x * v.x + v.y * v.y + v.z * v.z + v.w * v.w;
    }
#pragma unroll
    for (int off = 16; off; off >>= 1) ss += __shfl_xor_sync(~0u, ss, off);
    if ((tid & 31) == 0) red[tid >> 5] = ss;
    __syncthreads();
    float tot = 0.f;
#pragma unroll
    for (int i = 0; i < 8; i++) tot += red[i];
    float rs = rsqrtf(tot * (1.0f / DIM) + 1e-5f);
    const float4* wr = (const float4*)w;
    uint2* ohr = (uint2*)(oh + (size_t)row * DIM);
    uint2* olr = (uint2*)(ol + (size_t)row * DIM);
#pragma unroll
    for (int i = 0; i < 4; i++) {
        int c = tid + i * 256;
        float4 v = vals[i];
        float4 wv = wr[c];
        v.x *= rs * wv.x; v.y *= rs * wv.y; v.z *= rs * wv.z; v.w *= rs * wv.w;
        uint32_t h0, l0, h1, l1;
        cvt2(v.x, v.y, h0, l0);
        cvt2(v.z, v.w, h1, l1);
        ohr[c] = make_uint2(h0, h1);
        olr[c] = make_uint2(l0, l1);
    }
}

// ---------------- RoPE ----------------
__global__ void rotary_kernel(float* __restrict__ q, float* __restrict__ k,
                              const float* __restrict__ cosb,
                              const float* __restrict__ sinb) {
    float* t = blockIdx.y ? k : q;
    int idx = blockIdx.x * 256 + threadIdx.x;
    int s = idx >> 11;
    int rem = idx & 2047;
    int i = rem & 63;
    int h = rem >> 6;
    float c = cosb[s * 64 + i];
    float sn = sinb[s * 64 + i];
    size_t base = (size_t)s * DIM + h * HD + 2 * i;
    float x0 = t[base], x1 = t[base + 1];
    t[base] = x0 * c - x1 * sn;
    t[base + 1] = x0 * sn + x1 * c;
}

// ---------------- causal attention: warp per q-row, bf16 hi/lo out ---------
__global__ void __launch_bounds__(256) attn_kernel(const float* __restrict__ Q,
                                                   const float* __restrict__ K,
                                                   const float* __restrict__ V,
                                                   __nv_bfloat16* __restrict__ Oh,
                                                   __nv_bfloat16* __restrict__ Ol) {
    __shared__ float ks[32][128];
    __shared__ float vs[32][128];
    int h = blockIdx.y;
    int qt = blockIdx.x;
    int tid = threadIdx.x;
    int warp = tid >> 5, lane = tid & 31;
    int qrow = qt * 8 + warp;

    float4 qv = *(const float4*)(Q + (size_t)qrow * DIM + h * HD + lane * 4);
    float m = -1e30f, l = 0.f;
    float4 acc = {0.f, 0.f, 0.f, 0.f};
    int qmax = qt * 8 + 7;
    int nkb = qmax / 32 + 1;
    const float scale = 0.08838834764831845f;

    for (int kb = 0; kb < nkb; kb++) {
        __syncthreads();
#pragma unroll
        for (int i = 0; i < 4; i++) {
            int li = tid + i * 256;
            int rr = li >> 5;
            int c4 = li & 31;
            size_t gaddr = (size_t)(kb * 32 + rr) * DIM + h * HD;
            ((float4*)ks[rr])[c4] = ((const float4*)(K + gaddr))[c4];
            ((float4*)vs[rr])[c4] = ((const float4*)(V + gaddr))[c4];
        }
        __syncthreads();
        int jend = min(31, qrow - kb * 32);
        for (int j = 0; j <= jend; j++) {
            float4 kv = ((const float4*)ks[j])[lane];
            float s = qv.x * kv.x + qv.y * kv.y + qv.z * kv.z + qv.w * kv.w;
#pragma unroll
            for (int off = 16; off; off >>= 1) s += __shfl_xor_sync(~0u, s, off);
            s *= scale;
            float4 vv = ((const float4*)vs[j])[lane];
            if (s > m) {
                float c = __expf(m - s);
                l = l * c + 1.f;
                acc.x = acc.x * c + vv.x;
                acc.y = acc.y * c + vv.y;
                acc.z = acc.z * c + vv.z;
                acc.w = acc.w * c + vv.w;
                m = s;
            } else {
                float p = __expf(s - m);
                l += p;
                acc.x += p * vv.x; acc.y += p * vv.y;
                acc.z += p * vv.z; acc.w += p * vv.w;
            }
        }
    }
    float inv = 1.f / l;
    float4 o;
    o.x = acc.x * inv; o.y = acc.y * inv; o.z = acc.z * inv; o.w = acc.w * inv;
    uint32_t h0, l0, h1, l1;
    cvt2(o.x, o.y, h0, l0);
    cvt2(o.z, o.w, h1, l1);
    size_t idx = (size_t)qrow * DIM + h * HD + lane * 4;
    *(uint2*)(Oh + idx) = make_uint2(h0, h1);
    *(uint2*)(Ol + idx) = make_uint2(l0, l1);
}

// ---------------- SwiGLU -> bf16 hi/lo ----------------
__global__ void swiglu_bf(const float* __restrict__ g1, const float* __restrict__ g3,
                          __nv_bfloat16* __restrict__ oh,
                          __nv_bfloat16* __restrict__ ol, int n4) {
    int i = blockIdx.x * 256 + threadIdx.x;
    if (i < n4) {
        float4 a = ((const float4*)g1)[i];
        float4 b = ((const float4*)g3)[i];
        float4 r;
        r.x = a.x / (1.f + __expf(-a.x)) * b.x;
        r.y = a.y / (1.f + __expf(-a.y)) * b.y;
        r.z = a.z / (1.f + __expf(-a.z)) * b.z;
        r.w = a.w / (1.f + __expf(-a.w)) * b.w;
        uint32_t h0, l0, h1, l1;
        cvt2(r.x, r.y, h0, l0);
        cvt2(r.z, r.w, h1, l1);
        ((uint2*)oh)[i] = make_uint2(h0, h1);
        ((uint2*)ol)[i] = make_uint2(l0, l1);
    }
}

// ---------------- launch ----------------
extern "C" void kernel_launch(void* const* d_in, const int* in_sizes, int n_in,
                              void* d_out, int out_size) {
    const float* x   = (const float*)d_in[0];
    const float* fc  = (const float*)d_in[1];
    const float* fs  = (const float*)d_in[2];
    const float* anw = (const float*)d_in[4];
    const float* wq  = (const float*)d_in[5];
    const float* wk  = (const float*)d_in[6];
    const float* wv  = (const float*)d_in[7];
    const float* wo  = (const float*)d_in[8];
    const float* fnw = (const float*)d_in[9];
    const float* w1  = (const float*)d_in[10];
    const float* w2  = (const float*)d_in[11];
    const float* w3  = (const float*)d_in[12];
    float* out = (float*)d_out;

    float *q, *k, *v, *h, *g1, *g3;
    __nv_bfloat16 *xnh, *xnl, *ath, *atl, *gh, *gl;
    __nv_bfloat16 *wqh, *wql, *wkh, *wkl, *wvh, *wvl, *woh, *wol;
    __nv_bfloat16 *w1h, *w1l, *w3h, *w3l, *w2h, *w2l;
    cudaGetSymbolAddress((void**)&q,  g_q);
    cudaGetSymbolAddress((void**)&k,  g_k);
    cudaGetSymbolAddress((void**)&v,  g_v);
    cudaGetSymbolAddress((void**)&h,  g_h);
    cudaGetSymbolAddress((void**)&g1, g_g1);
    cudaGetSymbolAddress((void**)&g3, g_g3);
    cudaGetSymbolAddress((void**)&xnh, g_xnh);
    cudaGetSymbolAddress((void**)&xnl, g_xnl);
    cudaGetSymbolAddress((void**)&ath, g_ath);
    cudaGetSymbolAddress((void**)&atl, g_atl);
    cudaGetSymbolAddress((void**)&gh,  g_gh);
    cudaGetSymbolAddress((void**)&gl,  g_gl);
    cudaGetSymbolAddress((void**)&wqh, g_wqh);
    cudaGetSymbolAddress((void**)&wql, g_wql);
    cudaGetSymbolAddress((void**)&wkh, g_wkh);
    cudaGetSymbolAddress((void**)&wkl, g_wkl);
    cudaGetSymbolAddress((void**)&wvh, g_wvh);
    cudaGetSymbolAddress((void**)&wvl, g_wvl);
    cudaGetSymbolAddress((void**)&woh, g_woh);
    cudaGetSymbolAddress((void**)&wol, g_wol);
    cudaGetSymbolAddress((void**)&w1h, g_w1h);
    cudaGetSymbolAddress((void**)&w1l, g_w1l);
    cudaGetSymbolAddress((void**)&w3h, g_w3h);
    cudaGetSymbolAddress((void**)&w3l, g_w3l);
    cudaGetSymbolAddress((void**)&w2h, g_w2h);
    cudaGetSymbolAddress((void**)&w2l, g_w2l);

    cudaFuncSetAttribute(gemm_bf<0>, cudaFuncAttributeMaxDynamicSharedMemorySize, GEMM_SMEM);
    cudaFuncSetAttribute(gemm_bf<1>, cudaFuncAttributeMaxDynamicSharedMemorySize, GEMM_SMEM);

    const int ndd4 = DIM * DIM / 4;
    const int nhd4 = HID * DIM / 4;
    split_kernel<<<(ndd4 + 255) / 256, 256>>>(wq, wqh, wql, ndd4);
    split_kernel<<<(ndd4 + 255) / 256, 256>>>(wk, wkh, wkl, ndd4);
    split_kernel<<<(ndd4 + 255) / 256, 256>>>(wv, wvh, wvl, ndd4);
    split_kernel<<<(ndd4 + 255) / 256, 256>>>(wo, woh, wol, ndd4);
    split_kernel<<<(nhd4 + 255) / 256, 256>>>(w1, w1h, w1l, nhd4);
    split_kernel<<<(nhd4 + 255) / 256, 256>>>(w3, w3h, w3l, nhd4);
    split_kernel<<<(nhd4 + 255) / 256, 256>>>(w2, w2h, w2l, nhd4);

    dim3 gdd(DIM / 128, SEQ / 128);   // 32 x 16
    dim3 ghd(HID / 128, SEQ / 128);   // 86 x 16

    rmsnorm_bf<<<SEQ, 256>>>(x, anw, xnh, xnl);
    gemm_bf<0><<<gdd, 256, GEMM_SMEM>>>(xnh, xnl, wqh, wql, nullptr, q, SEQ, DIM, DIM);
    gemm_bf<0><<<gdd, 256, GEMM_SMEM>>>(xnh, xnl, wkh, wkl, nullptr, k, SEQ, DIM, DIM);
    gemm_bf<0><<<gdd, 256, GEMM_SMEM>>>(xnh, xnl, wvh, wvl, nullptr, v, SEQ, DIM, DIM);
    rotary_kernel<<<dim3(SEQ * NH * 64 / 256, 2), 256>>>(q, k, fc, fs);
    attn_kernel<<<dim3(SEQ / 8, NH), 256>>>(q, k, v, ath, atl);
    gemm_bf<1><<<gdd, 256, GEMM_SMEM>>>(ath, atl, woh, wol, x, h, SEQ, DIM, DIM);
    rmsnorm_bf<<<SEQ, 256>>>(h, fnw, xnh, xnl);
    gemm_bf<0><<<ghd, 256, GEMM_SMEM>>>(xnh, xnl, w1h, w1l, nullptr, g1, SEQ, HID, DIM);
    gemm_bf<0><<<ghd, 256, GEMM_SMEM>>>(xnh, xnl, w3h, w3l, nullptr, g3, SEQ, HID, DIM);
    swiglu_bf<<<(SEQ * HID / 4 + 255) / 256, 256>>>(g1, g3, gh, gl, SEQ * HID / 4);
    gemm_bf<1><<<gdd, 256, GEMM_SMEM>>>(gh, gl, w2h, w2l, h, out, SEQ, DIM, HID);
}

// round 10
// speedup vs baseline: 3.2189x; 1.2156x over previous
#include <cuda_runtime.h>
#include <cuda_fp16.h>
#include <cstdint>
#include <math.h>

#define SEQ 2048
#define DIM 4096
#define NH 32
#define HD 128
#define HID 11008

// ---------------- scratch (no cudaMalloc allowed) ----------------
__device__ float g_q[SEQ * DIM];
__device__ float g_k[SEQ * DIM];
__device__ float g_v[SEQ * DIM];
__device__ float g_h[SEQ * DIM];
__device__ float g_g1[SEQ * HID];
__device__ float g_g3[SEQ * HID];

__device__ __half g_xnh[SEQ * DIM];
__device__ __half g_ath[SEQ * DIM];
__device__ __half g_gh[SEQ * HID];

__device__ __half g_wqh[DIM * DIM], g_wql[DIM * DIM];
__device__ __half g_wkh[DIM * DIM], g_wkl[DIM * DIM];
__device__ __half g_wvh[DIM * DIM], g_wvl[DIM * DIM];
__device__ __half g_woh[DIM * DIM], g_wol[DIM * DIM];
__device__ __half g_w1h[HID * DIM], g_w1l[HID * DIM];
__device__ __half g_w3h[HID * DIM], g_w3l[HID * DIM];
__device__ __half g_w2h[DIM * HID], g_w2l[DIM * HID];

__device__ __forceinline__ uint32_t smem_u32(const void* p) {
    uint32_t a;
    asm("{ .reg .u64 t; cvta.to.shared.u64 t, %1; cvt.u32.u64 %0, t; }"
        : "=r"(a) : "l"(p));
    return a;
}

#define LDSM_X4(r, addr)                                                      \
    asm volatile("ldmatrix.sync.aligned.m8n8.x4.shared.b16 {%0,%1,%2,%3}, [%4];" \
                 : "=r"((r)[0]), "=r"((r)[1]), "=r"((r)[2]), "=r"((r)[3])     \
                 : "r"(addr))

#define MMA_FP16(d, a, b0, b1)                                                \
    asm volatile(                                                             \
        "mma.sync.aligned.m16n8k16.row.col.f32.f16.f16.f32 "                  \
        "{%0,%1,%2,%3},{%4,%5,%6,%7},{%8,%9},{%0,%1,%2,%3};"                  \
        : "+f"((d)[0]), "+f"((d)[1]), "+f"((d)[2]), "+f"((d)[3])              \
        : "r"((a)[0]), "r"((a)[1]), "r"((a)[2]), "r"((a)[3]), "r"(b0), "r"(b1))

#define CP16(dst, src)                                                        \
    asm volatile("cp.async.cg.shared.global [%0], [%1], 16;"                  \
                 :: "r"(dst), "l"(src))
#define CP_COMMIT() asm volatile("cp.async.commit_group;")
#define CP_WAIT(n)  asm volatile("cp.async.wait_group %0;" :: "n"(n))

// fp32 -> fp16 hi + lo residual (2 elems -> packed half2 words)
__device__ __forceinline__ void cvt2hl(float x0, float x1, uint32_t& h, uint32_t& l) {
    __half h0 = __float2half_rn(x0);
    __half h1 = __float2half_rn(x1);
    float r0 = x0 - __half2float(h0);
    float r1 = x1 - __half2float(h1);
    __half2 hh(h0, h1);
    __half2 ll(__float2half_rn(r0), __float2half_rn(r1));
    h = *(uint32_t*)&hh;
    l = *(uint32_t*)&ll;
}
// fp32x2 -> single fp16x2 word
__device__ __forceinline__ uint32_t cvt2h(float x0, float x1) {
    __half2 hh(__float2half_rn(x0), __float2half_rn(x1));
    return *(uint32_t*)&hh;
}

// smem row = 32 fp16 = 64B, 4 chunks of 16B, XOR-swizzled
__device__ __forceinline__ uint32_t swz(int r, uint32_t cb) {
    return (uint32_t)r * 64 + (cb ^ (((r >> 1) & 3) << 4));
}

// ===== GEMM: C = A * B^T (+R); A single fp16, B split fp16 hi/lo, 2 passes ==
// BM=BN=128, BK=32, 256 threads, warp grid 2x4, warp tile 64x32
// stage 24KB: A 0 | BH 8K | BL 16K ; 3 stages
#define STAGE_B 24576
#define GEMM_SMEM (3 * STAGE_B)

template <int RES>
__global__ void __launch_bounds__(256, 2) gemm_fp16(
    const __half* __restrict__ Ah,
    const __half* __restrict__ Bh, const __half* __restrict__ Bl,
    const float* __restrict__ R, float* __restrict__ C, int M, int N, int K) {
    extern __shared__ __align__(1024) char smem[];
    uint32_t sbase = smem_u32(smem);
    int tid = threadIdx.x;
    int lane = tid & 31, wid = tid >> 5;
    int wm = (wid >> 2) * 64;
    int wn = (wid & 3) * 32;
    int bm = blockIdx.y, bn = blockIdx.x;

    const __half* Ab  = Ah + (size_t)(bm * 128) * K;
    const __half* Bhb = Bh + (size_t)(bn * 128) * K;
    const __half* Blb = Bl + (size_t)(bn * 128) * K;
    int NS = K / 32;

#define ISSUE(s)                                                              \
    {                                                                         \
        int k0 = (s) * 32;                                                    \
        uint32_t sb = sbase + ((s) % 3) * STAGE_B;                            \
        _Pragma("unroll") for (int it = 0; it < 6; it++) {                    \
            int id = tid + (it & 1) * 256;                                    \
            int row = id >> 2, kc = id & 3;                                   \
            const __half* src =                                               \
                ((it >> 1) == 0 ? Ab : (it >> 1) == 1 ? Bhb : Blb) +          \
                (size_t)row * K + k0 + kc * 8;                                \
            uint32_t dst = sb + (uint32_t)(it >> 1) * 8192 +                  \
                           swz(row, (uint32_t)kc << 4);                       \
            CP16(dst, src);                                                   \
        }                                                                     \
        CP_COMMIT();                                                          \
    }

    float acc[4][4][4];
#pragma unroll
    for (int i = 0; i < 4; i++)
#pragma unroll
        for (int j = 0; j < 4; j++)
#pragma unroll
            for (int t = 0; t < 4; t++) acc[i][j][t] = 0.f;

    ISSUE(0);
    ISSUE(1);

    int sub = lane >> 3;
    for (int s = 0; s < NS; s++) {
        CP_WAIT(1);
        __syncthreads();
        if (s + 2 < NS) ISSUE(s + 2);
        uint32_t sb = sbase + (s % 3) * STAGE_B;
#pragma unroll
        for (int ks = 0; ks < 2; ks++) {
            uint32_t bh[8], bl[8];
#pragma unroll
            for (int np = 0; np < 2; np++) {
                int n = wn + np * 16 + (sub >> 1) * 8 + (lane & 7);
                uint32_t cb = (uint32_t)(ks * 2 + (sub & 1)) << 4;
                uint32_t off = swz(n, cb);
                LDSM_X4(&bh[np * 4], sb + 8192 + off);
                LDSM_X4(&bl[np * 4], sb + 16384 + off);
            }
#pragma unroll
            for (int mi = 0; mi < 4; mi++) {
                uint32_t a[4];
                int r = wm + mi * 16 + (lane & 7) + (sub & 1) * 8;
                uint32_t cb = (uint32_t)(ks * 2 + (sub >> 1)) << 4;
                uint32_t off = swz(r, cb);
                LDSM_X4(a, sb + off);
#pragma unroll
                for (int ni = 0; ni < 4; ni++) {
                    uint32_t* bp = &bh[(ni >> 1) * 4 + (ni & 1) * 2];
                    MMA_FP16(acc[mi][ni], a, bp[0], bp[1]);
                }
#pragma unroll
                for (int ni = 0; ni < 4; ni++) {
                    uint32_t* bp = &bl[(ni >> 1) * 4 + (ni & 1) * 2];
                    MMA_FP16(acc[mi][ni], a, bp[0], bp[1]);
                }
            }
        }
        __syncthreads();
    }

#pragma unroll
    for (int mi = 0; mi < 4; mi++)
#pragma unroll
        for (int ni = 0; ni < 4; ni++) {
            int r0 = bm * 128 + wm + mi * 16 + (lane >> 2);
            int col = bn * 128 + wn + ni * 8 + (lane & 3) * 2;
            float* p0 = C + (size_t)r0 * N + col;
            float* p1 = p0 + 8 * (size_t)N;
            float2 v0 = {acc[mi][ni][0], acc[mi][ni][1]};
            float2 v1 = {acc[mi][ni][2], acc[mi][ni][3]};
            if (RES) {
                const float* q0 = R + (size_t)r0 * N + col;
                const float* q1 = q0 + 8 * (size_t)N;
                v0.x += q0[0]; v0.y += q0[1];
                v1.x += q1[0]; v1.y += q1[1];
            }
            *(float2*)p0 = v0;
            *(float2*)p1 = v1;
        }
#undef ISSUE
}

// ---------------- weight split: fp32 -> fp16 hi/lo ----------------
__global__ void split_kernel(const float* __restrict__ w,
                             __half* __restrict__ h,
                             __half* __restrict__ l, int n4) {
    int i = blockIdx.x * 256 + threadIdx.x;
    if (i < n4) {
        float4 v = ((const float4*)w)[i];
        uint32_t h0, l0, h1, l1;
        cvt2hl(v.x, v.y, h0, l0);
        cvt2hl(v.z, v.w, h1, l1);
        ((uint2*)h)[i] = make_uint2(h0, h1);
        ((uint2*)l)[i] = make_uint2(l0, l1);
    }
}

// ---------------- RMSNorm -> single fp16 ----------------
__global__ void rmsnorm_h(const float* __restrict__ x,
                          const float* __restrict__ w,
                          __half* __restrict__ oh) {
    int row = blockIdx.x;
    int tid = threadIdx.x;
    const float4* xr = (const float4*)(x + (size_t)row * DIM);
    __shared__ float red[8];
    float4 vals[4];
    float ss = 0.f;
#pragma unroll
    for (int i = 0; i < 4; i++) {
        float4 v = xr[tid + i * 256];
        vals[i] = v;
        ss += v.x * v.x + v.y * v.y + v.z * v.z + v.w * v.w;
    }
#pragma unroll
    for (int off = 16; off; off >>= 1) ss += __shfl_xor_sync(~0u, ss, off);
    if ((tid & 31) == 0) red[tid >> 5] = ss;
    __syncthreads();
    float tot = 0.f;
#pragma unroll
    for (int i = 0; i < 8; i++) tot += red[i];
    float rs = rsqrtf(tot * (1.0f / DIM) + 1e-5f);
    const float4* wr = (const float4*)w;
    uint2* ohr = (uint2*)(oh + (size_t)row * DIM);
#pragma unroll
    for (int i = 0; i < 4; i++) {
        int c = tid + i * 256;
        float4 v = vals[i];
        float4 wv = wr[c];
        v.x *= rs * wv.x; v.y *= rs * wv.y; v.z *= rs * wv.z; v.w *= rs * wv.w;
        ohr[c] = make_uint2(cvt2h(v.x, v.y), cvt2h(v.z, v.w));
    }
}

// ---------------- RoPE ----------------
__global__ void rotary_kernel(float* __restrict__ q, float* __restrict__ k,
                              const float* __restrict__ cosb,
                              const float* __restrict__ sinb) {
    float* t = blockIdx.y ? k : q;
    int idx = blockIdx.x * 256 + threadIdx.x;
    int s = idx >> 11;
    int rem = idx & 2047;
    int i = rem & 63;
    int h = rem >> 6;
    float c = cosb[s * 64 + i];
    float sn = sinb[s * 64 + i];
    size_t base = (size_t)s * DIM + h * HD + 2 * i;
    float x0 = t[base], x1 = t[base + 1];
    t[base] = x0 * c - x1 * sn;
    t[base + 1] = x0 * sn + x1 * c;
}

// ---------------- causal attention: warp per q-row, fp16 out ---------------
__global__ void __launch_bounds__(256) attn_kernel(const float* __restrict__ Q,
                                                   const float* __restrict__ K,
                                                   const float* __restrict__ V,
                                                   __half* __restrict__ Oh) {
    __shared__ float ks[32][128];
    __shared__ float vs[32][128];
    int h = blockIdx.y;
    int qt = blockIdx.x;
    int tid = threadIdx.x;
    int warp = tid >> 5, lane = tid & 31;
    int qrow = qt * 8 + warp;

    float4 qv = *(const float4*)(Q + (size_t)qrow * DIM + h * HD + lane * 4);
    float m = -1e30f, l = 0.f;
    float4 acc = {0.f, 0.f, 0.f, 0.f};
    int qmax = qt * 8 + 7;
    int nkb = qmax / 32 + 1;
    const float scale = 0.08838834764831845f;

    for (int kb = 0; kb < nkb; kb++) {
        __syncthreads();
#pragma unroll
        for (int i = 0; i < 4; i++) {
            int li = tid + i * 256;
            int rr = li >> 5;
            int c4 = li & 31;
            size_t gaddr = (size_t)(kb * 32 + rr) * DIM + h * HD;
            ((float4*)ks[rr])[c4] = ((const float4*)(K + gaddr))[c4];
            ((float4*)vs[rr])[c4] = ((const float4*)(V + gaddr))[c4];
        }
        __syncthreads();
        int jend = min(31, qrow - kb * 32);
        for (int j = 0; j <= jend; j++) {
            float4 kv = ((const float4*)ks[j])[lane];
            float s = qv.x * kv.x + qv.y * kv.y + qv.z * kv.z + qv.w * kv.w;
#pragma unroll
            for (int off = 16; off; off >>= 1) s += __shfl_xor_sync(~0u, s, off);
            s *= scale;
            float4 vv = ((const float4*)vs[j])[lane];
            if (s > m) {
                float c = __expf(m - s);
                l = l * c + 1.f;
                acc.x = acc.x * c + vv.x;
                acc.y = acc.y * c + vv.y;
                acc.z = acc.z * c + vv.z;
                acc.w = acc.w * c + vv.w;
                m = s;
            } else {
                float p = __expf(s - m);
                l += p;
                acc.x += p * vv.x; acc.y += p * vv.y;
                acc.z += p * vv.z; acc.w += p * vv.w;
            }
        }
    }
    float inv = 1.f / l;
    size_t idx = (size_t)qrow * DIM + h * HD + lane * 4;
    *(uint2*)(Oh + idx) =
        make_uint2(cvt2h(acc.x * inv, acc.y * inv), cvt2h(acc.z * inv, acc.w * inv));
}

// ---------------- SwiGLU -> single fp16 ----------------
__global__ void swiglu_h(const float* __restrict__ g1, const float* __restrict__ g3,
                         __half* __restrict__ oh, int n4) {
    int i = blockIdx.x * 256 + threadIdx.x;
    if (i < n4) {
        float4 a = ((const float4*)g1)[i];
        float4 b = ((const float4*)g3)[i];
        float4 r;
        r.x = a.x / (1.f + __expf(-a.x)) * b.x;
        r.y = a.y / (1.f + __expf(-a.y)) * b.y;
        r.z = a.z / (1.f + __expf(-a.z)) * b.z;
        r.w = a.w / (1.f + __expf(-a.w)) * b.w;
        ((uint2*)oh)[i] = make_uint2(cvt2h(r.x, r.y), cvt2h(r.z, r.w));
    }
}

// ---------------- launch ----------------
extern "C" void kernel_launch(void* const* d_in, const int* in_sizes, int n_in,
                              void* d_out, int out_size) {
    const float* x   = (const float*)d_in[0];
    const float* fc  = (const float*)d_in[1];
    const float* fs  = (const float*)d_in[2];
    const float* anw = (const float*)d_in[4];
    const float* wq  = (const float*)d_in[5];
    const float* wk  = (const float*)d_in[6];
    const float* wv  = (const float*)d_in[7];
    const float* wo  = (const float*)d_in[8];
    const float* fnw = (const float*)d_in[9];
    const float* w1  = (const float*)d_in[10];
    const float* w2  = (const float*)d_in[11];
    const float* w3  = (const float*)d_in[12];
    float* out = (float*)d_out;

    float *q, *k, *v, *h, *g1, *g3;
    __half *xnh, *ath, *gh;
    __half *wqh, *wql, *wkh, *wkl, *wvh, *wvl, *woh, *wol;
    __half *w1h, *w1l, *w3h, *w3l, *w2h, *w2l;
    cudaGetSymbolAddress((void**)&q,  g_q);
    cudaGetSymbolAddress((void**)&k,  g_k);
    cudaGetSymbolAddress((void**)&v,  g_v);
    cudaGetSymbolAddress((void**)&h,  g_h);
    cudaGetSymbolAddress((void**)&g1, g_g1);
    cudaGetSymbolAddress((void**)&g3, g_g3);
    cudaGetSymbolAddress((void**)&xnh, g_xnh);
    cudaGetSymbolAddress((void**)&ath, g_ath);
    cudaGetSymbolAddress((void**)&gh,  g_gh);
    cudaGetSymbolAddress((void**)&wqh, g_wqh);
    cudaGetSymbolAddress((void**)&wql, g_wql);
    cudaGetSymbolAddress((void**)&wkh, g_wkh);
    cudaGetSymbolAddress((void**)&wkl, g_wkl);
    cudaGetSymbolAddress((void**)&wvh, g_wvh);
    cudaGetSymbolAddress((void**)&wvl, g_wvl);
    cudaGetSymbolAddress((void**)&woh, g_woh);
    cudaGetSymbolAddress((void**)&wol, g_wol);
    cudaGetSymbolAddress((void**)&w1h, g_w1h);
    cudaGetSymbolAddress((void**)&w1l, g_w1l);
    cudaGetSymbolAddress((void**)&w3h, g_w3h);
    cudaGetSymbolAddress((void**)&w3l, g_w3l);
    cudaGetSymbolAddress((void**)&w2h, g_w2h);
    cudaGetSymbolAddress((void**)&w2l, g_w2l);

    cudaFuncSetAttribute(gemm_fp16<0>, cudaFuncAttributeMaxDynamicSharedMemorySize, GEMM_SMEM);
    cudaFuncSetAttribute(gemm_fp16<1>, cudaFuncAttributeMaxDynamicSharedMemorySize, GEMM_SMEM);

    const int ndd4 = DIM * DIM / 4;
    const int nhd4 = HID * DIM / 4;
    split_kernel<<<(ndd4 + 255) / 256, 256>>>(wq, wqh, wql, ndd4);
    split_kernel<<<(ndd4 + 255) / 256, 256>>>(wk, wkh, wkl, ndd4);
    split_kernel<<<(ndd4 + 255) / 256, 256>>>(wv, wvh, wvl, ndd4);
    split_kernel<<<(ndd4 + 255) / 256, 256>>>(wo, woh, wol, ndd4);
    split_kernel<<<(nhd4 + 255) / 256, 256>>>(w1, w1h, w1l, nhd4);
    split_kernel<<<(nhd4 + 255) / 256, 256>>>(w3, w3h, w3l, nhd4);
    split_kernel<<<(nhd4 + 255) / 256, 256>>>(w2, w2h, w2l, nhd4);

    dim3 gdd(DIM / 128, SEQ / 128);   // 32 x 16
    dim3 ghd(HID / 128, SEQ / 128);   // 86 x 16

    rmsnorm_h<<<SEQ, 256>>>(x, anw, xnh);
    gemm_fp16<0><<<gdd, 256, GEMM_SMEM>>>(xnh, wqh, wql, nullptr, q, SEQ, DIM, DIM);
    gemm_fp16<0><<<gdd, 256, GEMM_SMEM>>>(xnh, wkh, wkl, nullptr, k, SEQ, DIM, DIM);
    gemm_fp16<0><<<gdd, 256, GEMM_SMEM>>>(xnh, wvh, wvl, nullptr, v, SEQ, DIM, DIM);
    rotary_kernel<<<dim3(SEQ * NH * 64 / 256, 2), 256>>>(q, k, fc, fs);
    attn_kernel<<<dim3(SEQ / 8, NH), 256>>>(q, k, v, ath);
    gemm_fp16<1><<<gdd, 256, GEMM_SMEM>>>(ath, woh, wol, x, h, SEQ, DIM, DIM);
    rmsnorm_h<<<SEQ, 256>>>(h, fnw, xnh);
    gemm_fp16<0><<<ghd, 256, GEMM_SMEM>>>(xnh, w1h, w1l, nullptr, g1, SEQ, HID, DIM);
    gemm_fp16<0><<<ghd, 256, GEMM_SMEM>>>(xnh, w3h, w3l, nullptr, g3, SEQ, HID, DIM);
    swiglu_h<<<(SEQ * HID / 4 + 255) / 256, 256>>>(g1, g3, gh, SEQ * HID / 4);
    gemm_fp16<1><<<gdd, 256, GEMM_SMEM>>>(gh, w2h, w2l, h, out, SEQ, DIM, HID);
}

// round 11
// speedup vs baseline: 4.2442x; 1.3185x over previous
#include <cuda_runtime.h>
#include <cuda_fp16.h>
#include <cstdint>
#include <math.h>

#define SEQ 2048
#define DIM 4096
#define NH 32
#define HD 128
#define HID 11008

// ---------------- scratch (no cudaMalloc allowed) ----------------
__device__ float g_q[SEQ * DIM];
__device__ float g_k[SEQ * DIM];
__device__ float g_v[SEQ * DIM];
__device__ float g_h[SEQ * DIM];
__device__ float g_g1[SEQ * HID];
__device__ float g_g3[SEQ * HID];

__device__ __half g_xnh[SEQ * DIM];
__device__ __half g_ath[SEQ * DIM];
__device__ __half g_gh[SEQ * HID];

__device__ __half g_wqh[DIM * DIM];
__device__ __half g_wkh[DIM * DIM];
__device__ __half g_wvh[DIM * DIM];
__device__ __half g_woh[DIM * DIM];
__device__ __half g_w1h[HID * DIM];
__device__ __half g_w3h[HID * DIM];
__device__ __half g_w2h[DIM * HID];

__device__ __forceinline__ uint32_t smem_u32(const void* p) {
    uint32_t a;
    asm("{ .reg .u64 t; cvta.to.shared.u64 t, %1; cvt.u32.u64 %0, t; }"
        : "=r"(a) : "l"(p));
    return a;
}

#define LDSM_X4(r, addr)                                                      \
    asm volatile("ldmatrix.sync.aligned.m8n8.x4.shared.b16 {%0,%1,%2,%3}, [%4];" \
                 : "=r"((r)[0]), "=r"((r)[1]), "=r"((r)[2]), "=r"((r)[3])     \
                 : "r"(addr))

#define MMA_FP16(d, a, b0, b1)                                                \
    asm volatile(                                                             \
        "mma.sync.aligned.m16n8k16.row.col.f32.f16.f16.f32 "                  \
        "{%0,%1,%2,%3},{%4,%5,%6,%7},{%8,%9},{%0,%1,%2,%3};"                  \
        : "+f"((d)[0]), "+f"((d)[1]), "+f"((d)[2]), "+f"((d)[3])              \
        : "r"((a)[0]), "r"((a)[1]), "r"((a)[2]), "r"((a)[3]), "r"(b0), "r"(b1))

#define CP16(dst, src)                                                        \
    asm volatile("cp.async.cg.shared.global [%0], [%1], 16;"                  \
                 :: "r"(dst), "l"(src))
#define CP_COMMIT() asm volatile("cp.async.commit_group;")
#define CP_WAIT(n)  asm volatile("cp.async.wait_group %0;" :: "n"(n))

// fp32x2 -> single fp16x2 word
__device__ __forceinline__ uint32_t cvt2h(float x0, float x1) {
    __half2 hh(__float2half_rn(x0), __float2half_rn(x1));
    return *(uint32_t*)&hh;
}

// smem row = 32 fp16 = 64B, 4 chunks of 16B, XOR-swizzled
__device__ __forceinline__ uint32_t swz(int r, uint32_t cb) {
    return (uint32_t)r * 64 + (cb ^ (((r >> 1) & 3) << 4));
}

// ===== GEMM: C = A * B^T (+R); pure fp16 operands, fp32 accum ==============
// BM=BN=128, BK=32, 256 threads, warp grid 2x4, warp tile 64x32
// stage 16KB: A 0 | B 8K ; 3 stages
#define STAGE_B 16384
#define GEMM_SMEM (3 * STAGE_B)

template <int RES>
__global__ void __launch_bounds__(256, 2) gemm_fp16(
    const __half* __restrict__ Ah, const __half* __restrict__ Bh,
    const float* __restrict__ R, float* __restrict__ C, int M, int N, int K) {
    extern __shared__ __align__(1024) char smem[];
    uint32_t sbase = smem_u32(smem);
    int tid = threadIdx.x;
    int lane = tid & 31, wid = tid >> 5;
    int wm = (wid >> 2) * 64;
    int wn = (wid & 3) * 32;
    int bm = blockIdx.y, bn = blockIdx.x;

    const __half* Ab = Ah + (size_t)(bm * 128) * K;
    const __half* Bb = Bh + (size_t)(bn * 128) * K;
    int NS = K / 32;

#define ISSUE(s)                                                              \
    {                                                                         \
        int k0 = (s) * 32;                                                    \
        uint32_t sb = sbase + ((s) % 3) * STAGE_B;                            \
        _Pragma("unroll") for (int it = 0; it < 4; it++) {                    \
            int id = tid + (it & 1) * 256;                                    \
            int row = id >> 2, kc = id & 3;                                   \
            const __half* src = ((it >> 1) == 0 ? Ab : Bb) +                  \
                                (size_t)row * K + k0 + kc * 8;                \
            uint32_t dst = sb + (uint32_t)(it >> 1) * 8192 +                  \
                           swz(row, (uint32_t)kc << 4);                       \
            CP16(dst, src);                                                   \
        }                                                                     \
        CP_COMMIT();                                                          \
    }

    float acc[4][4][4];
#pragma unroll
    for (int i = 0; i < 4; i++)
#pragma unroll
        for (int j = 0; j < 4; j++)
#pragma unroll
            for (int t = 0; t < 4; t++) acc[i][j][t] = 0.f;

    ISSUE(0);
    ISSUE(1);

    int sub = lane >> 3;
    for (int s = 0; s < NS; s++) {
        CP_WAIT(1);
        __syncthreads();
        if (s + 2 < NS) ISSUE(s + 2);
        uint32_t sb = sbase + (s % 3) * STAGE_B;
#pragma unroll
        for (int ks = 0; ks < 2; ks++) {
            uint32_t bh[8];
#pragma unroll
            for (int np = 0; np < 2; np++) {
                int n = wn + np * 16 + (sub >> 1) * 8 + (lane & 7);
                uint32_t cb = (uint32_t)(ks * 2 + (sub & 1)) << 4;
                uint32_t off = swz(n, cb);
                LDSM_X4(&bh[np * 4], sb + 8192 + off);
            }
#pragma unroll
            for (int mi = 0; mi < 4; mi++) {
                uint32_t a[4];
                int r = wm + mi * 16 + (lane & 7) + (sub & 1) * 8;
                uint32_t cb = (uint32_t)(ks * 2 + (sub >> 1)) << 4;
                uint32_t off = swz(r, cb);
                LDSM_X4(a, sb + off);
#pragma unroll
                for (int ni = 0; ni < 4; ni++) {
                    uint32_t* bp = &bh[(ni >> 1) * 4 + (ni & 1) * 2];
                    MMA_FP16(acc[mi][ni], a, bp[0], bp[1]);
                }
            }
        }
        __syncthreads();
    }

#pragma unroll
    for (int mi = 0; mi < 4; mi++)
#pragma unroll
        for (int ni = 0; ni < 4; ni++) {
            int r0 = bm * 128 + wm + mi * 16 + (lane >> 2);
            int col = bn * 128 + wn + ni * 8 + (lane & 3) * 2;
            float* p0 = C + (size_t)r0 * N + col;
            float* p1 = p0 + 8 * (size_t)N;
            float2 v0 = {acc[mi][ni][0], acc[mi][ni][1]};
            float2 v1 = {acc[mi][ni][2], acc[mi][ni][3]};
            if (RES) {
                const float* q0 = R + (size_t)r0 * N + col;
                const float* q1 = q0 + 8 * (size_t)N;
                v0.x += q0[0]; v0.y += q0[1];
                v1.x += q1[0]; v1.y += q1[1];
            }
            *(float2*)p0 = v0;
            *(float2*)p1 = v1;
        }
#undef ISSUE
}

// ---------------- weight convert: fp32 -> fp16 ----------------
__global__ void convert_kernel(const float* __restrict__ w,
                               __half* __restrict__ h, int n4) {
    int i = blockIdx.x * 256 + threadIdx.x;
    if (i < n4) {
        float4 v = ((const float4*)w)[i];
        ((uint2*)h)[i] = make_uint2(cvt2h(v.x, v.y), cvt2h(v.z, v.w));
    }
}

// ---------------- RMSNorm -> single fp16 ----------------
__global__ void rmsnorm_h(const float* __restrict__ x,
                          const float* __restrict__ w,
                          __half* __restrict__ oh) {
    int row = blockIdx.x;
    int tid = threadIdx.x;
    const float4* xr = (const float4*)(x + (size_t)row * DIM);
    __shared__ float red[8];
    float4 vals[4];
    float ss = 0.f;
#pragma unroll
    for (int i = 0; i < 4; i++) {
        float4 v = xr[tid + i * 256];
        vals[i] = v;
        ss += v.x * v.x + v.y * v.y + v.z * v.z + v.w * v.w;
    }
#pragma unroll
    for (int off = 16; off; off >>= 1) ss += __shfl_xor_sync(~0u, ss, off);
    if ((tid & 31) == 0) red[tid >> 5] = ss;
    __syncthreads();
    float tot = 0.f;
#pragma unroll
    for (int i = 0; i < 8; i++) tot += red[i];
    float rs = rsqrtf(tot * (1.0f / DIM) + 1e-5f);
    const float4* wr = (const float4*)w;
    uint2* ohr = (uint2*)(oh + (size_t)row * DIM);
#pragma unroll
    for (int i = 0; i < 4; i++) {
        int c = tid + i * 256;
        float4 v = vals[i];
        float4 wv = wr[c];
        v.x *= rs * wv.x; v.y *= rs * wv.y; v.z *= rs * wv.z; v.w *= rs * wv.w;
        ohr[c] = make_uint2(cvt2h(v.x, v.y), cvt2h(v.z, v.w));
    }
}

// ---------------- RoPE ----------------
__global__ void rotary_kernel(float* __restrict__ q, float* __restrict__ k,
                              const float* __restrict__ cosb,
                              const float* __restrict__ sinb) {
    float* t = blockIdx.y ? k : q;
    int idx = blockIdx.x * 256 + threadIdx.x;
    int s = idx >> 11;
    int rem = idx & 2047;
    int i = rem & 63;
    int h = rem >> 6;
    float c = cosb[s * 64 + i];
    float sn = sinb[s * 64 + i];
    size_t base = (size_t)s * DIM + h * HD + 2 * i;
    float x0 = t[base], x1 = t[base + 1];
    t[base] = x0 * c - x1 * sn;
    t[base + 1] = x0 * sn + x1 * c;
}

// ---------------- causal attention: warp per q-row, fp16 out ---------------
__global__ void __launch_bounds__(256) attn_kernel(const float* __restrict__ Q,
                                                   const float* __restrict__ K,
                                                   const float* __restrict__ V,
                                                   __half* __restrict__ Oh) {
    __shared__ float ks[32][128];
    __shared__ float vs[32][128];
    int h = blockIdx.y;
    int qt = blockIdx.x;
    int tid = threadIdx.x;
    int warp = tid >> 5, lane = tid & 31;
    int qrow = qt * 8 + warp;

    float4 qv = *(const float4*)(Q + (size_t)qrow * DIM + h * HD + lane * 4);
    float m = -1e30f, l = 0.f;
    float4 acc = {0.f, 0.f, 0.f, 0.f};
    int qmax = qt * 8 + 7;
    int nkb = qmax / 32 + 1;
    const float scale = 0.08838834764831845f;

    for (int kb = 0; kb < nkb; kb++) {
        __syncthreads();
#pragma unroll
        for (int i = 0; i < 4; i++) {
            int li = tid + i * 256;
            int rr = li >> 5;
            int c4 = li & 31;
            size_t gaddr = (size_t)(kb * 32 + rr) * DIM + h * HD;
            ((float4*)ks[rr])[c4] = ((const float4*)(K + gaddr))[c4];
            ((float4*)vs[rr])[c4] = ((const float4*)(V + gaddr))[c4];
        }
        __syncthreads();
        int jend = min(31, qrow - kb * 32);
        for (int j = 0; j <= jend; j++) {
            float4 kv = ((const float4*)ks[j])[lane];
            float s = qv.x * kv.x + qv.y * kv.y + qv.z * kv.z + qv.w * kv.w;
#pragma unroll
            for (int off = 16; off; off >>= 1) s += __shfl_xor_sync(~0u, s, off);
            s *= scale;
            float4 vv = ((const float4*)vs[j])[lane];
            if (s > m) {
                float c = __expf(m - s);
                l = l * c + 1.f;
                acc.x = acc.x * c + vv.x;
                acc.y = acc.y * c + vv.y;
                acc.z = acc.z * c + vv.z;
                acc.w = acc.w * c + vv.w;
                m = s;
            } else {
                float p = __expf(s - m);
                l += p;
                acc.x += p * vv.x; acc.y += p * vv.y;
                acc.z += p * vv.z; acc.w += p * vv.w;
            }
        }
    }
    float inv = 1.f / l;
    size_t idx = (size_t)qrow * DIM + h * HD + lane * 4;
    *(uint2*)(Oh + idx) =
        make_uint2(cvt2h(acc.x * inv, acc.y * inv), cvt2h(acc.z * inv, acc.w * inv));
}

// ---------------- SwiGLU -> single fp16 ----------------
__global__ void swiglu_h(const float* __restrict__ g1, const float* __restrict__ g3,
                         __half* __restrict__ oh, int n4) {
    int i = blockIdx.x * 256 + threadIdx.x;
    if (i < n4) {
        float4 a = ((const float4*)g1)[i];
        float4 b = ((const float4*)g3)[i];
        float4 r;
        r.x = a.x / (1.f + __expf(-a.x)) * b.x;
        r.y = a.y / (1.f + __expf(-a.y)) * b.y;
        r.z = a.z / (1.f + __expf(-a.z)) * b.z;
        r.w = a.w / (1.f + __expf(-a.w)) * b.w;
        ((uint2*)oh)[i] = make_uint2(cvt2h(r.x, r.y), cvt2h(r.z, r.w));
    }
}

// ---------------- launch ----------------
extern "C" void kernel_launch(void* const* d_in, const int* in_sizes, int n_in,
                              void* d_out, int out_size) {
    const float* x   = (const float*)d_in[0];
    const float* fc  = (const float*)d_in[1];
    const float* fs  = (const float*)d_in[2];
    const float* anw = (const float*)d_in[4];
    const float* wq  = (const float*)d_in[5];
    const float* wk  = (const float*)d_in[6];
    const float* wv  = (const float*)d_in[7];
    const float* wo  = (const float*)d_in[8];
    const float* fnw = (const float*)d_in[9];
    const float* w1  = (const float*)d_in[10];
    const float* w2  = (const float*)d_in[11];
    const float* w3  = (const float*)d_in[12];
    float* out = (float*)d_out;

    float *q, *k, *v, *h, *g1, *g3;
    __half *xnh, *ath, *gh;
    __half *wqh, *wkh, *wvh, *woh, *w1h, *w3h, *w2h;
    cudaGetSymbolAddress((void**)&q,  g_q);
    cudaGetSymbolAddress((void**)&k,  g_k);
    cudaGetSymbolAddress((void**)&v,  g_v);
    cudaGetSymbolAddress((void**)&h,  g_h);
    cudaGetSymbolAddress((void**)&g1, g_g1);
    cudaGetSymbolAddress((void**)&g3, g_g3);
    cudaGetSymbolAddress((void**)&xnh, g_xnh);
    cudaGetSymbolAddress((void**)&ath, g_ath);
    cudaGetSymbolAddress((void**)&gh,  g_gh);
    cudaGetSymbolAddress((void**)&wqh, g_wqh);
    cudaGetSymbolAddress((void**)&wkh, g_wkh);
    cudaGetSymbolAddress((void**)&wvh, g_wvh);
    cudaGetSymbolAddress((void**)&woh, g_woh);
    cudaGetSymbolAddress((void**)&w1h, g_w1h);
    cudaGetSymbolAddress((void**)&w3h, g_w3h);
    cudaGetSymbolAddress((void**)&w2h, g_w2h);

    cudaFuncSetAttribute(gemm_fp16<0>, cudaFuncAttributeMaxDynamicSharedMemorySize, GEMM_SMEM);
    cudaFuncSetAttribute(gemm_fp16<1>, cudaFuncAttributeMaxDynamicSharedMemorySize, GEMM_SMEM);

    const int ndd4 = DIM * DIM / 4;
    const int nhd4 = HID * DIM / 4;
    convert_kernel<<<(ndd4 + 255) / 256, 256>>>(wq, wqh, ndd4);
    convert_kernel<<<(ndd4 + 255) / 256, 256>>>(wk, wkh, ndd4);
    convert_kernel<<<(ndd4 + 255) / 256, 256>>>(wv, wvh, ndd4);
    convert_kernel<<<(ndd4 + 255) / 256, 256>>>(wo, woh, ndd4);
    convert_kernel<<<(nhd4 + 255) / 256, 256>>>(w1, w1h, nhd4);
    convert_kernel<<<(nhd4 + 255) / 256, 256>>>(w3, w3h, nhd4);
    convert_kernel<<<(nhd4 + 255) / 256, 256>>>(w2, w2h, nhd4);

    dim3 gdd(DIM / 128, SEQ / 128);   // 32 x 16
    dim3 ghd(HID / 128, SEQ / 128);   // 86 x 16

    rmsnorm_h<<<SEQ, 256>>>(x, anw, xnh);
    gemm_fp16<0><<<gdd, 256, GEMM_SMEM>>>(xnh, wqh, nullptr, q, SEQ, DIM, DIM);
    gemm_fp16<0><<<gdd, 256, GEMM_SMEM>>>(xnh, wkh, nullptr, k, SEQ, DIM, DIM);
    gemm_fp16<0><<<gdd, 256, GEMM_SMEM>>>(xnh, wvh, nullptr, v, SEQ, DIM, DIM);
    rotary_kernel<<<dim3(SEQ * NH * 64 / 256, 2), 256>>>(q, k, fc, fs);
    attn_kernel<<<dim3(SEQ / 8, NH), 256>>>(q, k, v, ath);
    gemm_fp16<1><<<gdd, 256, GEMM_SMEM>>>(ath, woh, x, h, SEQ, DIM, DIM);
    rmsnorm_h<<<SEQ, 256>>>(h, fnw, xnh);
    gemm_fp16<0><<<ghd, 256, GEMM_SMEM>>>(xnh, w1h, nullptr, g1, SEQ, HID, DIM);
    gemm_fp16<0><<<ghd, 256, GEMM_SMEM>>>(xnh, w3h, nullptr, g3, SEQ, HID, DIM);
    swiglu_h<<<(SEQ * HID / 4 + 255) / 256, 256>>>(g1, g3, gh, SEQ * HID / 4);
    gemm_fp16<1><<<gdd, 256, GEMM_SMEM>>>(gh, w2h, h, out, SEQ, DIM, HID);
}

// round 12
// speedup vs baseline: 9.7644x; 2.3006x over previous
#include <cuda_runtime.h>
#include <cuda_fp16.h>
#include <cstdint>
#include <math.h>

#define SEQ 2048
#define DIM 4096
#define NH 32
#define HD 128
#define HID 11008

// ---------------- scratch (no cudaMalloc allowed) ----------------
__device__ float g_h[SEQ * DIM];
__device__ __half g_xnh[SEQ * DIM];
__device__ __half g_qkvh[SEQ * 3 * DIM];
__device__ __half g_ath[SEQ * DIM];
__device__ __half g_g13h[SEQ * 2 * HID];
__device__ __half g_gh[SEQ * HID];
__device__ __half g_wqkvh[3 * DIM * DIM];
__device__ __half g_woh[DIM * DIM];
__device__ __half g_w13h[2 * HID * DIM];
__device__ __half g_w2h[DIM * HID];

__device__ __forceinline__ uint32_t smem_u32(const void* p) {
    uint32_t a;
    asm("{ .reg .u64 t; cvta.to.shared.u64 t, %1; cvt.u32.u64 %0, t; }"
        : "=r"(a) : "l"(p));
    return a;
}

#define LDSM_X4(r, addr)                                                      \
    asm volatile("ldmatrix.sync.aligned.m8n8.x4.shared.b16 {%0,%1,%2,%3}, [%4];" \
                 : "=r"((r)[0]), "=r"((r)[1]), "=r"((r)[2]), "=r"((r)[3])     \
                 : "r"(addr))
#define LDSM_X4_T(r, addr)                                                    \
    asm volatile("ldmatrix.sync.aligned.m8n8.x4.trans.shared.b16 {%0,%1,%2,%3}, [%4];" \
                 : "=r"((r)[0]), "=r"((r)[1]), "=r"((r)[2]), "=r"((r)[3])     \
                 : "r"(addr))

#define MMA_FP16(d, a, b0, b1)                                                \
    asm volatile(                                                             \
        "mma.sync.aligned.m16n8k16.row.col.f32.f16.f16.f32 "                  \
        "{%0,%1,%2,%3},{%4,%5,%6,%7},{%8,%9},{%0,%1,%2,%3};"                  \
        : "+f"((d)[0]), "+f"((d)[1]), "+f"((d)[2]), "+f"((d)[3])              \
        : "r"((a)[0]), "r"((a)[1]), "r"((a)[2]), "r"((a)[3]), "r"(b0), "r"(b1))

#define CP16(dst, src)                                                        \
    asm volatile("cp.async.cg.shared.global [%0], [%1], 16;"                  \
                 :: "r"(dst), "l"(src))
#define CP_COMMIT() asm volatile("cp.async.commit_group;")
#define CP_WAIT(n)  asm volatile("cp.async.wait_group %0;" :: "n"(n))

__device__ __forceinline__ uint32_t cvt2h(float x0, float x1) {
    __half2 hh(__float2half_rn(x0), __float2half_rn(x1));
    return *(uint32_t*)&hh;
}
// 64B-row swizzle (GEMM tiles)
__device__ __forceinline__ uint32_t swz(int r, uint32_t cb) {
    return (uint32_t)r * 64 + (cb ^ (((r >> 1) & 3) << 4));
}
// 128B-row swizzle (attention tiles)
__device__ __forceinline__ uint32_t sw128_(uint32_t x) { return x ^ ((x >> 3) & 0x70); }

// ===== GEMM: C = A * B^T (+R); pure fp16 operands, fp32 accum ==============
#define STAGE_B 16384
#define GEMM_SMEM (3 * STAGE_B)

template <int RES, int OUTH>
__global__ void __launch_bounds__(256, 2) gemm_fp16(
    const __half* __restrict__ Ah, const __half* __restrict__ Bh,
    const float* __restrict__ R, void* __restrict__ Cv, int M, int N, int K) {
    extern __shared__ __align__(1024) char smem[];
    uint32_t sbase = smem_u32(smem);
    int tid = threadIdx.x;
    int lane = tid & 31, wid = tid >> 5;
    int wm = (wid >> 2) * 64;
    int wn = (wid & 3) * 32;
    int bm = blockIdx.y, bn = blockIdx.x;

    const __half* Ab = Ah + (size_t)(bm * 128) * K;
    const __half* Bb = Bh + (size_t)(bn * 128) * K;
    int NS = K / 32;

#define ISSUE(s)                                                              \
    {                                                                         \
        int k0 = (s) * 32;                                                    \
        uint32_t sb = sbase + ((s) % 3) * STAGE_B;                            \
        _Pragma("unroll") for (int it = 0; it < 4; it++) {                    \
            int id = tid + (it & 1) * 256;                                    \
            int row = id >> 2, kc = id & 3;                                   \
            const __half* src = ((it >> 1) == 0 ? Ab : Bb) +                  \
                                (size_t)row * K + k0 + kc * 8;                \
            uint32_t dst = sb + (uint32_t)(it >> 1) * 8192 +                  \
                           swz(row, (uint32_t)kc << 4);                       \
            CP16(dst, src);                                                   \
        }                                                                     \
        CP_COMMIT();                                                          \
    }

    float acc[4][4][4];
#pragma unroll
    for (int i = 0; i < 4; i++)
#pragma unroll
        for (int j = 0; j < 4; j++)
#pragma unroll
            for (int t = 0; t < 4; t++) acc[i][j][t] = 0.f;

    ISSUE(0);
    ISSUE(1);

    int sub = lane >> 3;
    for (int s = 0; s < NS; s++) {
        CP_WAIT(1);
        __syncthreads();
        if (s + 2 < NS) ISSUE(s + 2);
        uint32_t sb = sbase + (s % 3) * STAGE_B;
#pragma unroll
        for (int ks = 0; ks < 2; ks++) {
            uint32_t bh[8];
#pragma unroll
            for (int np = 0; np < 2; np++) {
                int n = wn + np * 16 + (sub >> 1) * 8 + (lane & 7);
                uint32_t cb = (uint32_t)(ks * 2 + (sub & 1)) << 4;
                LDSM_X4(&bh[np * 4], sb + 8192 + swz(n, cb));
            }
#pragma unroll
            for (int mi = 0; mi < 4; mi++) {
                uint32_t a[4];
                int r = wm + mi * 16 + (lane & 7) + (sub & 1) * 8;
                uint32_t cb = (uint32_t)(ks * 2 + (sub >> 1)) << 4;
                LDSM_X4(a, sb + swz(r, cb));
#pragma unroll
                for (int ni = 0; ni < 4; ni++) {
                    uint32_t* bp = &bh[(ni >> 1) * 4 + (ni & 1) * 2];
                    MMA_FP16(acc[mi][ni], a, bp[0], bp[1]);
                }
            }
        }
        __syncthreads();
    }

#pragma unroll
    for (int mi = 0; mi < 4; mi++)
#pragma unroll
        for (int ni = 0; ni < 4; ni++) {
            int r0 = bm * 128 + wm + mi * 16 + (lane >> 2);
            int col = bn * 128 + wn + ni * 8 + (lane & 3) * 2;
            if (OUTH) {
                __half* C = (__half*)Cv;
                *(uint32_t*)(C + (size_t)r0 * N + col) =
                    cvt2h(acc[mi][ni][0], acc[mi][ni][1]);
                *(uint32_t*)(C + (size_t)(r0 + 8) * N + col) =
                    cvt2h(acc[mi][ni][2], acc[mi][ni][3]);
            } else {
                float* C = (float*)Cv;
                float* p0 = C + (size_t)r0 * N + col;
                float* p1 = p0 + 8 * (size_t)N;
                float2 v0 = {acc[mi][ni][0], acc[mi][ni][1]};
                float2 v1 = {acc[mi][ni][2], acc[mi][ni][3]};
                if (RES) {
                    const float* q0 = R + (size_t)r0 * N + col;
                    const float* q1 = q0 + 8 * (size_t)N;
                    v0.x += q0[0]; v0.y += q0[1];
                    v1.x += q1[0]; v1.y += q1[1];
                }
                *(float2*)p0 = v0;
                *(float2*)p1 = v1;
            }
        }
#undef ISSUE
}

// ---------------- weight convert: fp32 -> fp16 ----------------
__global__ void convert_kernel(const float* __restrict__ w,
                               __half* __restrict__ h, int n4) {
    int i = blockIdx.x * 256 + threadIdx.x;
    if (i < n4) {
        float4 v = ((const float4*)w)[i];
        ((uint2*)h)[i] = make_uint2(cvt2h(v.x, v.y), cvt2h(v.z, v.w));
    }
}

// ---------------- RMSNorm -> fp16 ----------------
__global__ void rmsnorm_h(const float* __restrict__ x,
                          const float* __restrict__ w,
                          __half* __restrict__ oh) {
    int row = blockIdx.x;
    int tid = threadIdx.x;
    const float4* xr = (const float4*)(x + (size_t)row * DIM);
    __shared__ float red[8];
    float4 vals[4];
    float ss = 0.f;
#pragma unroll
    for (int i = 0; i < 4; i++) {
        float4 v = xr[tid + i * 256];
        vals[i] = v;
        ss += v.x * v.x + v.y * v.y + v.z * v.z + v.w * v.w;
    }
#pragma unroll
    for (int off = 16; off; off >>= 1) ss += __shfl_xor_sync(~0u, ss, off);
    if ((tid & 31) == 0) red[tid >> 5] = ss;
    __syncthreads();
    float tot = 0.f;
#pragma unroll
    for (int i = 0; i < 8; i++) tot += red[i];
    float rs = rsqrtf(tot * (1.0f / DIM) + 1e-5f);
    const float4* wr = (const float4*)w;
    uint2* ohr = (uint2*)(oh + (size_t)row * DIM);
#pragma unroll
    for (int i = 0; i < 4; i++) {
        int c = tid + i * 256;
        float4 v = vals[i];
        float4 wv = wr[c];
        v.x *= rs * wv.x; v.y *= rs * wv.y; v.z *= rs * wv.z; v.w *= rs * wv.w;
        ohr[c] = make_uint2(cvt2h(v.x, v.y), cvt2h(v.z, v.w));
    }
}

// ---------------- RoPE on fp16 qkv; Q also scaled by log2e/sqrt(hd) --------
#define QSCALE 0.12751744935309278f
__global__ void rotary_h(__half* __restrict__ qkv,
                         const float* __restrict__ cosb,
                         const float* __restrict__ sinb) {
    int idx = blockIdx.x * 256 + threadIdx.x;
    int s = idx >> 11;
    int rem = idx & 2047;
    int i = rem & 63;
    int hh = rem >> 6;
    float c = cosb[s * 64 + i];
    float sn = sinb[s * 64 + i];
    size_t base = (size_t)s * (3 * DIM) + blockIdx.y * DIM + hh * HD + 2 * i;
    __half2* p = (__half2*)(qkv + base);
    float2 v = __half22float2(*p);
    float o0 = v.x * c - v.y * sn;
    float o1 = v.x * sn + v.y * c;
    if (blockIdx.y == 0) { o0 *= QSCALE; o1 *= QSCALE; }
    *p = __floats2half2_rn(o0, o1);
}

// ---------------- flash attention (fp16 MMA, online softmax) ---------------
// BQ=128 (8 warps x m16), BKV=64, hd=128. smem: Q 32K | K/V double buf 4x16K
#define FA_SMEM 98304

__global__ void __launch_bounds__(256, 1) flash_attn(
    const __half* __restrict__ QKV, __half* __restrict__ O) {
    extern __shared__ __align__(1024) char smem[];
    uint32_t sb = smem_u32(smem);
    int tid = threadIdx.x, lane = tid & 31, w = tid >> 5;
    int h = blockIdx.y, qb = blockIdx.x;
    int qbase = qb * 128;
    const int LD = 3 * DIM;

    const __half* Qg = QKV + (size_t)qbase * LD + h * HD;
    const __half* Kg = QKV + DIM + h * HD;
    const __half* Vg = QKV + 2 * DIM + h * HD;

#define ISSUE_KV(i, b)                                                        \
    {                                                                         \
        int kv0_ = (i) * 64;                                                  \
        uint32_t kb_ = sb + 32768 + (b) * 32768;                              \
        _Pragma("unroll") for (int it = 0; it < 4; it++) {                    \
            int id = tid + it * 256;                                          \
            int row = id >> 4, ch = id & 15;                                  \
            uint32_t o_ = (uint32_t)(ch >> 3) * 8192 +                        \
                          sw128_(row * 128 + (ch & 7) * 16);                  \
            const __half* ksrc = Kg + (size_t)(kv0_ + row) * LD + ch * 8;     \
            const __half* vsrc = Vg + (size_t)(kv0_ + row) * LD + ch * 8;     \
            CP16(kb_ + o_, ksrc);                                             \
            CP16(kb_ + 16384 + o_, vsrc);                                     \
        }                                                                     \
    }

    // Q tile: 128 rows, 2048 chunks
#pragma unroll
    for (int it = 0; it < 8; it++) {
        int id = tid + it * 256;
        int row = id >> 4, ch = id & 15;
        uint32_t dst = sb + (uint32_t)(ch >> 3) * 16384 +
                       sw128_(row * 128 + (ch & 7) * 16);
        CP16(dst, Qg + (size_t)row * LD + ch * 8);
    }
    ISSUE_KV(0, 0);
    CP_COMMIT();

    float oacc[16][4];
#pragma unroll
    for (int j = 0; j < 16; j++)
#pragma unroll
        for (int t = 0; t < 4; t++) oacc[j][t] = 0.f;
    float m0 = -1e30f, m1 = -1e30f, l0 = 0.f, l1 = 0.f;
    uint32_t qf[8][4];

    int nkb = qb * 2 + 2;
    int sub = lane >> 3;
    int wrow = qbase + w * 16;

    for (int i = 0; i < nkb; i++) {
        int b = i & 1;
        if (i + 1 < nkb) {
            ISSUE_KV(i + 1, b ^ 1);
            CP_COMMIT();
            CP_WAIT(1);
        } else {
            CP_WAIT(0);
        }
        __syncthreads();
        if (i == 0) {
#pragma unroll
            for (int kt = 0; kt < 8; kt++) {
                int r = w * 16 + (lane & 7) + (sub & 1) * 8;
                uint32_t ch = (uint32_t)((kt & 3) * 2 + (sub >> 1));
                uint32_t addr = sb + (uint32_t)(kt >> 2) * 16384 +
                                sw128_(r * 128 + ch * 16);
                LDSM_X4(qf[kt], addr);
            }
        }
        int kv0 = i * 64;
        if (kv0 <= wrow + 15) {
            float sacc[8][4];
#pragma unroll
            for (int j = 0; j < 8; j++)
#pragma unroll
                for (int t = 0; t < 4; t++) sacc[j][t] = 0.f;
            uint32_t Kb = sb + 32768 + b * 32768;
            // S = Q K^T
#pragma unroll
            for (int ng = 0; ng < 4; ng++) {
                int nr = ng * 16 + (sub >> 1) * 8 + (lane & 7);
#pragma unroll
                for (int kt = 0; kt < 8; kt++) {
                    uint32_t bb[4];
                    uint32_t ch = (uint32_t)((kt & 3) * 2 + (sub & 1));
                    uint32_t addr = Kb + (uint32_t)(kt >> 2) * 8192 +
                                    sw128_(nr * 128 + ch * 16);
                    LDSM_X4(bb, addr);
                    MMA_FP16(sacc[ng * 2], qf[kt], bb[0], bb[1]);
                    MMA_FP16(sacc[ng * 2 + 1], qf[kt], bb[2], bb[3]);
                }
            }
            int r0 = wrow + (lane >> 2), r1 = r0 + 8;
            if (kv0 + 63 > r0) {
#pragma unroll
                for (int j = 0; j < 8; j++) {
                    int c = kv0 + j * 8 + 2 * (lane & 3);
                    if (c > r0) sacc[j][0] = -1e30f;
                    if (c + 1 > r0) sacc[j][1] = -1e30f;
                    if (c > r1) sacc[j][2] = -1e30f;
                    if (c + 1 > r1) sacc[j][3] = -1e30f;
                }
            }
            // online softmax (base-2; scale folded into Q)
            float mx0 = -1e30f, mx1 = -1e30f;
#pragma unroll
            for (int j = 0; j < 8; j++) {
                mx0 = fmaxf(mx0, fmaxf(sacc[j][0], sacc[j][1]));
                mx1 = fmaxf(mx1, fmaxf(sacc[j][2], sacc[j][3]));
            }
            mx0 = fmaxf(mx0, __shfl_xor_sync(~0u, mx0, 1));
            mx0 = fmaxf(mx0, __shfl_xor_sync(~0u, mx0, 2));
            mx1 = fmaxf(mx1, __shfl_xor_sync(~0u, mx1, 1));
            mx1 = fmaxf(mx1, __shfl_xor_sync(~0u, mx1, 2));
            float m0n = fmaxf(m0, mx0), m1n = fmaxf(m1, mx1);
            float c0 = exp2f(m0 - m0n), c1 = exp2f(m1 - m1n);
            float rs0 = 0.f, rs1 = 0.f;
#pragma unroll
            for (int j = 0; j < 8; j++) {
                sacc[j][0] = exp2f(sacc[j][0] - m0n);
                sacc[j][1] = exp2f(sacc[j][1] - m0n);
                sacc[j][2] = exp2f(sacc[j][2] - m1n);
                sacc[j][3] = exp2f(sacc[j][3] - m1n);
                rs0 += sacc[j][0] + sacc[j][1];
                rs1 += sacc[j][2] + sacc[j][3];
            }
            rs0 += __shfl_xor_sync(~0u, rs0, 1);
            rs0 += __shfl_xor_sync(~0u, rs0, 2);
            rs1 += __shfl_xor_sync(~0u, rs1, 1);
            rs1 += __shfl_xor_sync(~0u, rs1, 2);
            l0 = l0 * c0 + rs0;
            l1 = l1 * c1 + rs1;
            m0 = m0n;
            m1 = m1n;
#pragma unroll
            for (int j = 0; j < 16; j++) {
                oacc[j][0] *= c0; oacc[j][1] *= c0;
                oacc[j][2] *= c1; oacc[j][3] *= c1;
            }
            // O += P V
            uint32_t Vb = Kb + 16384;
#pragma unroll
            for (int kt = 0; kt < 4; kt++) {
                uint32_t a[4];
                a[0] = cvt2h(sacc[2 * kt][0], sacc[2 * kt][1]);
                a[1] = cvt2h(sacc[2 * kt][2], sacc[2 * kt][3]);
                a[2] = cvt2h(sacc[2 * kt + 1][0], sacc[2 * kt + 1][1]);
                a[3] = cvt2h(sacc[2 * kt + 1][2], sacc[2 * kt + 1][3]);
                int kr = kt * 16 + (lane & 7) + ((lane >> 3) & 1) * 8;
#pragma unroll
                for (int dp = 0; dp < 8; dp++) {
                    int dim = dp * 16 + ((lane >> 4) & 1) * 8;
                    uint32_t addr = Vb + (uint32_t)(dim >> 6) * 8192 +
                                    sw128_(kr * 128 + ((dim & 63) >> 3) * 16);
                    uint32_t vv[4];
                    LDSM_X4_T(vv, addr);
                    MMA_FP16(oacc[dp * 2], a, vv[0], vv[1]);
                    MMA_FP16(oacc[dp * 2 + 1], a, vv[2], vv[3]);
                }
            }
        }
        __syncthreads();
    }

    float i0 = 1.f / l0, i1 = 1.f / l1;
    int r0g = qbase + w * 16 + (lane >> 2);
#pragma unroll
    for (int j = 0; j < 16; j++) {
        int col = h * HD + j * 8 + 2 * (lane & 3);
        *(uint32_t*)(O + (size_t)r0g * DIM + col) =
            cvt2h(oacc[j][0] * i0, oacc[j][1] * i0);
        *(uint32_t*)(O + (size_t)(r0g + 8) * DIM + col) =
            cvt2h(oacc[j][2] * i1, oacc[j][3] * i1);
    }
#undef ISSUE_KV
}

// ---------------- SwiGLU on fused g13 -> fp16 ----------------
__global__ void swiglu2(const __half* __restrict__ g13, __half* __restrict__ oh) {
    int s = blockIdx.x;
    int j4 = blockIdx.y * 256 + threadIdx.x;
    if (j4 < HID / 4) {
        const __half2* p1 = (const __half2*)(g13 + (size_t)s * (2 * HID) + j4 * 4);
        const __half2* p3 = (const __half2*)(g13 + (size_t)s * (2 * HID) + HID + j4 * 4);
        float2 a0 = __half22float2(p1[0]), a1 = __half22float2(p1[1]);
        float2 b0 = __half22float2(p3[0]), b1 = __half22float2(p3[1]);
        float r0 = a0.x / (1.f + __expf(-a0.x)) * b0.x;
        float r1 = a0.y / (1.f + __expf(-a0.y)) * b0.y;
        float r2 = a1.x / (1.f + __expf(-a1.x)) * b1.x;
        float r3 = a1.y / (1.f + __expf(-a1.y)) * b1.y;
        *(uint2*)(oh + (size_t)s * HID + j4 * 4) =
            make_uint2(cvt2h(r0, r1), cvt2h(r2, r3));
    }
}

// ---------------- launch ----------------
extern "C" void kernel_launch(void* const* d_in, const int* in_sizes, int n_in,
                              void* d_out, int out_size) {
    const float* x   = (const float*)d_in[0];
    const float* fc  = (const float*)d_in[1];
    const float* fs  = (const float*)d_in[2];
    const float* anw = (const float*)d_in[4];
    const float* wq  = (const float*)d_in[5];
    const float* wk  = (const float*)d_in[6];
    const float* wv  = (const float*)d_in[7];
    const float* wo  = (const float*)d_in[8];
    const float* fnw = (const float*)d_in[9];
    const float* w1  = (const float*)d_in[10];
    const float* w2  = (const float*)d_in[11];
    const float* w3  = (const float*)d_in[12];
    float* out = (float*)d_out;

    float* h;
    __half *xnh, *qkvh, *ath, *g13h, *gh;
    __half *wqkvh, *woh, *w13h, *w2h;
    cudaGetSymbolAddress((void**)&h,     g_h);
    cudaGetSymbolAddress((void**)&xnh,   g_xnh);
    cudaGetSymbolAddress((void**)&qkvh,  g_qkvh);
    cudaGetSymbolAddress((void**)&ath,   g_ath);
    cudaGetSymbolAddress((void**)&g13h,  g_g13h);
    cudaGetSymbolAddress((void**)&gh,    g_gh);
    cudaGetSymbolAddress((void**)&wqkvh, g_wqkvh);
    cudaGetSymbolAddress((void**)&woh,   g_woh);
    cudaGetSymbolAddress((void**)&w13h,  g_w13h);
    cudaGetSymbolAddress((void**)&w2h,   g_w2h);

    cudaFuncSetAttribute(gemm_fp16<0, 1>, cudaFuncAttributeMaxDynamicSharedMemorySize, GEMM_SMEM);
    cudaFuncSetAttribute(gemm_fp16<1, 0>, cudaFuncAttributeMaxDynamicSharedMemorySize, GEMM_SMEM);
    cudaFuncSetAttribute(flash_attn, cudaFuncAttributeMaxDynamicSharedMemorySize, FA_SMEM);

    const int ndd4 = DIM * DIM / 4;
    const int nhd4 = HID * DIM / 4;
    convert_kernel<<<(ndd4 + 255) / 256, 256>>>(wq, wqkvh, ndd4);
    convert_kernel<<<(ndd4 + 255) / 256, 256>>>(wk, wqkvh + (size_t)DIM * DIM, ndd4);
    convert_kernel<<<(ndd4 + 255) / 256, 256>>>(wv, wqkvh + (size_t)2 * DIM * DIM, ndd4);
    convert_kernel<<<(ndd4 + 255) / 256, 256>>>(wo, woh, ndd4);
    convert_kernel<<<(nhd4 + 255) / 256, 256>>>(w1, w13h, nhd4);
    convert_kernel<<<(nhd4 + 255) / 256, 256>>>(w3, w13h + (size_t)HID * DIM, nhd4);
    convert_kernel<<<(nhd4 + 255) / 256, 256>>>(w2, w2h, nhd4);

    // 1. xn = rmsnorm(x)
    rmsnorm_h<<<SEQ, 256>>>(x, anw, xnh);
    // 2. qkv = xn @ [wq;wk;wv]^T (fp16 out)
    gemm_fp16<0, 1><<<dim3(3 * DIM / 128, SEQ / 128), 256, GEMM_SMEM>>>(
        xnh, wqkvh, nullptr, qkvh, SEQ, 3 * DIM, DIM);
    // 3. rope (q scaled by log2e/sqrt(hd))
    rotary_h<<<dim3(SEQ * NH * 64 / 256, 2), 256>>>(qkvh, fc, fs);
    // 4. flash attention
    flash_attn<<<dim3(SEQ / 128, NH), 256, FA_SMEM>>>(qkvh, ath);
    // 5. h = x + attn @ wo^T
    gemm_fp16<1, 0><<<dim3(DIM / 128, SEQ / 128), 256, GEMM_SMEM>>>(
        ath, woh, x, h, SEQ, DIM, DIM);
    // 6. hn = rmsnorm(h)
    rmsnorm_h<<<SEQ, 256>>>(h, fnw, xnh);
    // 7. g13 = hn @ [w1;w3]^T (fp16 out)
    gemm_fp16<0, 1><<<dim3(2 * HID / 128, SEQ / 128), 256, GEMM_SMEM>>>(
        xnh, w13h, nullptr, g13h, SEQ, 2 * HID, DIM);
    // 8. g = silu(g1) * g3
    swiglu2<<<dim3(SEQ, 11), 256>>>(g13h, gh);
    // 9. out = h + g @ w2^T
    gemm_fp16<1, 0><<<dim3(DIM / 128, SEQ / 128), 256, GEMM_SMEM>>>(
        gh, w2h, h, out, SEQ, DIM, HID);
}

// round 13
// speedup vs baseline: 9.9690x; 1.0210x over previous
#include <cuda_runtime.h>
#include <cuda_fp16.h>
#include <cstdint>
#include <math.h>

#define SEQ 2048
#define DIM 4096
#define NH 32
#define HD 128
#define HID 11008

// ---------------- scratch (no cudaMalloc allowed) ----------------
__device__ float g_h[SEQ * DIM];
__device__ __half g_xnh[SEQ * DIM];
__device__ __half g_qkvh[SEQ * 3 * DIM];
__device__ __half g_ath[SEQ * DIM];
__device__ __half g_gh[SEQ * HID];
__device__ __half g_wqkvh[3 * DIM * DIM];
__device__ __half g_woh[DIM * DIM];
__device__ __half g_w13h[2 * HID * DIM];
__device__ __half g_w2h[DIM * HID];

__device__ __forceinline__ uint32_t smem_u32(const void* p) {
    uint32_t a;
    asm("{ .reg .u64 t; cvta.to.shared.u64 t, %1; cvt.u32.u64 %0, t; }"
        : "=r"(a) : "l"(p));
    return a;
}

#define LDSM_X4(r, addr)                                                      \
    asm volatile("ldmatrix.sync.aligned.m8n8.x4.shared.b16 {%0,%1,%2,%3}, [%4];" \
                 : "=r"((r)[0]), "=r"((r)[1]), "=r"((r)[2]), "=r"((r)[3])     \
                 : "r"(addr))
#define LDSM_X4_T(r, addr)                                                    \
    asm volatile("ldmatrix.sync.aligned.m8n8.x4.trans.shared.b16 {%0,%1,%2,%3}, [%4];" \
                 : "=r"((r)[0]), "=r"((r)[1]), "=r"((r)[2]), "=r"((r)[3])     \
                 : "r"(addr))

#define MMA_FP16(d, a, b0, b1)                                                \
    asm volatile(                                                             \
        "mma.sync.aligned.m16n8k16.row.col.f32.f16.f16.f32 "                  \
        "{%0,%1,%2,%3},{%4,%5,%6,%7},{%8,%9},{%0,%1,%2,%3};"                  \
        : "+f"((d)[0]), "+f"((d)[1]), "+f"((d)[2]), "+f"((d)[3])              \
        : "r"((a)[0]), "r"((a)[1]), "r"((a)[2]), "r"((a)[3]), "r"(b0), "r"(b1))

#define CP16(dst, src)                                                        \
    asm volatile("cp.async.cg.shared.global [%0], [%1], 16;"                  \
                 :: "r"(dst), "l"(src))
#define CP_COMMIT() asm volatile("cp.async.commit_group;")
#define CP_WAIT(n)  asm volatile("cp.async.wait_group %0;" :: "n"(n))

__device__ __forceinline__ uint32_t cvt2h(float x0, float x1) {
    __half2 hh(__float2half_rn(x0), __float2half_rn(x1));
    return *(uint32_t*)&hh;
}
// 64B-row swizzle (GEMM tiles)
__device__ __forceinline__ uint32_t swz(int r, uint32_t cb) {
    return (uint32_t)r * 64 + (cb ^ (((r >> 1) & 3) << 4));
}
// 128B-row swizzle (attention tiles)
__device__ __forceinline__ uint32_t sw128_(uint32_t x) { return x ^ ((x >> 3) & 0x70); }

// ===== Persistent GEMM: C = A * B^T; MODE 0: fp32+res, 1: fp16, 2: swiglu ==
#define STAGE_B 16384
#define GEMM_SMEM (3 * STAGE_B)
#define GEMM_GRID 296

template <int MODE>
__global__ void __launch_bounds__(256, 2) gemm_p(
    const __half* __restrict__ Ah, const __half* __restrict__ Bh,
    const float* __restrict__ R, void* __restrict__ Cv, int M, int N, int K) {
    extern __shared__ __align__(1024) char smem[];
    uint32_t sbase = smem_u32(smem);
    int tid = threadIdx.x;
    int lane = tid & 31, wid = tid >> 5;
    int wm = (wid >> 2) * 64;
    int wn = (wid & 3) * 32;
    int nbm = M >> 7, nbn = N >> 7;
    int ntiles = nbm * nbn;
    int NS = K / 32;
    int sub = lane >> 3;

    for (int t = blockIdx.x; t < ntiles; t += gridDim.x) {
        int bm = t % nbm, bn = t / nbm;  // bm-fast: A panel stays in L2
        const __half* Ab = Ah + (size_t)(bm * 128) * K;
        const __half* Bb = Bh + (size_t)(bn * 128) * K;

#define ISSUE(s)                                                              \
    {                                                                         \
        int k0 = (s) * 32;                                                    \
        uint32_t sb = sbase + ((s) % 3) * STAGE_B;                            \
        _Pragma("unroll") for (int it = 0; it < 4; it++) {                    \
            int id = tid + (it & 1) * 256;                                    \
            int row = id >> 2, kc = id & 3;                                   \
            const __half* src = ((it >> 1) == 0 ? Ab : Bb) +                  \
                                (size_t)row * K + k0 + kc * 8;                \
            uint32_t dst = sb + (uint32_t)(it >> 1) * 8192 +                  \
                           swz(row, (uint32_t)kc << 4);                       \
            CP16(dst, src);                                                   \
        }                                                                     \
        CP_COMMIT();                                                          \
    }

        float acc[4][4][4];
#pragma unroll
        for (int i = 0; i < 4; i++)
#pragma unroll
            for (int j = 0; j < 4; j++)
#pragma unroll
                for (int tt = 0; tt < 4; tt++) acc[i][j][tt] = 0.f;

        ISSUE(0);
        ISSUE(1);

        for (int s = 0; s < NS; s++) {
            if (s + 1 < NS) { CP_WAIT(1); } else { CP_WAIT(0); }
            __syncthreads();
            if (s + 2 < NS) ISSUE(s + 2);
            uint32_t sb = sbase + (s % 3) * STAGE_B;
#pragma unroll
            for (int ks = 0; ks < 2; ks++) {
                uint32_t bh[8];
#pragma unroll
                for (int np = 0; np < 2; np++) {
                    int n = wn + np * 16 + (sub >> 1) * 8 + (lane & 7);
                    uint32_t cb = (uint32_t)(ks * 2 + (sub & 1)) << 4;
                    LDSM_X4(&bh[np * 4], sb + 8192 + swz(n, cb));
                }
#pragma unroll
                for (int mi = 0; mi < 4; mi++) {
                    uint32_t a[4];
                    int r = wm + mi * 16 + (lane & 7) + (sub & 1) * 8;
                    uint32_t cb = (uint32_t)(ks * 2 + (sub >> 1)) << 4;
                    LDSM_X4(a, sb + swz(r, cb));
#pragma unroll
                    for (int ni = 0; ni < 4; ni++) {
                        uint32_t* bp = &bh[(ni >> 1) * 4 + (ni & 1) * 2];
                        MMA_FP16(acc[mi][ni], a, bp[0], bp[1]);
                    }
                }
            }
            __syncthreads();
        }

        if (MODE == 2) {
            // swiglu epilogue: interleaved w13 rows -> g = silu(g1)*g3
            __half* C = (__half*)Cv;
            int outN = N >> 1;
#pragma unroll
            for (int mi = 0; mi < 4; mi++)
#pragma unroll
                for (int p = 0; p < 2; p++) {
                    int n0 = bn * 128 + wn + p * 16 + 2 * (lane & 3);
                    int j = ((n0 >> 4) << 3) + (n0 & 7);
                    int r0 = bm * 128 + wm + mi * 16 + (lane >> 2);
                    float a0 = acc[mi][2 * p][0], a1 = acc[mi][2 * p][1];
                    float a2 = acc[mi][2 * p][2], a3 = acc[mi][2 * p][3];
                    float b0 = acc[mi][2 * p + 1][0], b1 = acc[mi][2 * p + 1][1];
                    float b2 = acc[mi][2 * p + 1][2], b3 = acc[mi][2 * p + 1][3];
                    float g0 = a0 / (1.f + __expf(-a0)) * b0;
                    float g1 = a1 / (1.f + __expf(-a1)) * b1;
                    float g2 = a2 / (1.f + __expf(-a2)) * b2;
                    float g3 = a3 / (1.f + __expf(-a3)) * b3;
                    *(uint32_t*)(C + (size_t)r0 * outN + j) = cvt2h(g0, g1);
                    *(uint32_t*)(C + (size_t)(r0 + 8) * outN + j) = cvt2h(g2, g3);
                }
        } else {
#pragma unroll
            for (int mi = 0; mi < 4; mi++)
#pragma unroll
                for (int ni = 0; ni < 4; ni++) {
                    int r0 = bm * 128 + wm + mi * 16 + (lane >> 2);
                    int col = bn * 128 + wn + ni * 8 + (lane & 3) * 2;
                    if (MODE == 1) {
                        __half* C = (__half*)Cv;
                        *(uint32_t*)(C + (size_t)r0 * N + col) =
                            cvt2h(acc[mi][ni][0], acc[mi][ni][1]);
                        *(uint32_t*)(C + (size_t)(r0 + 8) * N + col) =
                            cvt2h(acc[mi][ni][2], acc[mi][ni][3]);
                    } else {
                        float* C = (float*)Cv;
                        float* p0 = C + (size_t)r0 * N + col;
                        float* p1 = p0 + 8 * (size_t)N;
                        const float* q0 = R + (size_t)r0 * N + col;
                        const float* q1 = q0 + 8 * (size_t)N;
                        float2 v0 = {acc[mi][ni][0] + q0[0], acc[mi][ni][1] + q0[1]};
                        float2 v1 = {acc[mi][ni][2] + q1[0], acc[mi][ni][3] + q1[1]};
                        *(float2*)p0 = v0;
                        *(float2*)p1 = v1;
                    }
                }
        }
#undef ISSUE
    }
}

// ---------------- weight convert: fp32 -> fp16 ----------------
__global__ void convert_kernel(const float* __restrict__ w,
                               __half* __restrict__ h, int n4) {
    int i = blockIdx.x * 256 + threadIdx.x;
    if (i < n4) {
        float4 v = ((const float4*)w)[i];
        ((uint2*)h)[i] = make_uint2(cvt2h(v.x, v.y), cvt2h(v.z, v.w));
    }
}

// w1/w3 -> interleaved w13 (8-row blocks: [w1 j..j+7][w3 j..j+7])
__global__ void convert_w13(const float* __restrict__ w1,
                            const float* __restrict__ w3,
                            __half* __restrict__ o, int n4) {
    int i = blockIdx.x * 256 + threadIdx.x;
    if (i < n4) {
        int row = i / (DIM / 4);
        int c4 = i % (DIM / 4);
        int orow = ((row >> 3) << 4) + (row & 7);
        float4 v = ((const float4*)w1)[i];
        ((uint2*)(o + (size_t)orow * DIM))[c4] =
            make_uint2(cvt2h(v.x, v.y), cvt2h(v.z, v.w));
        float4 u = ((const float4*)w3)[i];
        ((uint2*)(o + (size_t)(orow + 8) * DIM))[c4] =
            make_uint2(cvt2h(u.x, u.y), cvt2h(u.z, u.w));
    }
}

// ---------------- RMSNorm -> fp16 ----------------
__global__ void rmsnorm_h(const float* __restrict__ x,
                          const float* __restrict__ w,
                          __half* __restrict__ oh) {
    int row = blockIdx.x;
    int tid = threadIdx.x;
    const float4* xr = (const float4*)(x + (size_t)row * DIM);
    __shared__ float red[8];
    float4 vals[4];
    float ss = 0.f;
#pragma unroll
    for (int i = 0; i < 4; i++) {
        float4 v = xr[tid + i * 256];
        vals[i] = v;
        ss += v.x * v.x + v.y * v.y + v.z * v.z + v.w * v.w;
    }
#pragma unroll
    for (int off = 16; off; off >>= 1) ss += __shfl_xor_sync(~0u, ss, off);
    if ((tid & 31) == 0) red[tid >> 5] = ss;
    __syncthreads();
    float tot = 0.f;
#pragma unroll
    for (int i = 0; i < 8; i++) tot += red[i];
    float rs = rsqrtf(tot * (1.0f / DIM) + 1e-5f);
    const float4* wr = (const float4*)w;
    uint2* ohr = (uint2*)(oh + (size_t)row * DIM);
#pragma unroll
    for (int i = 0; i < 4; i++) {
        int c = tid + i * 256;
        float4 v = vals[i];
        float4 wv = wr[c];
        v.x *= rs * wv.x; v.y *= rs * wv.y; v.z *= rs * wv.z; v.w *= rs * wv.w;
        ohr[c] = make_uint2(cvt2h(v.x, v.y), cvt2h(v.z, v.w));
    }
}

// ---------------- RoPE on fp16 qkv; Q also scaled by log2e/sqrt(hd) --------
#define QSCALE 0.12751744935309278f
__global__ void rotary_h(__half* __restrict__ qkv,
                         const float* __restrict__ cosb,
                         const float* __restrict__ sinb) {
    int idx = blockIdx.x * 256 + threadIdx.x;
    int s = idx >> 11;
    int rem = idx & 2047;
    int i = rem & 63;
    int hh = rem >> 6;
    float c = cosb[s * 64 + i];
    float sn = sinb[s * 64 + i];
    size_t base = (size_t)s * (3 * DIM) + blockIdx.y * DIM + hh * HD + 2 * i;
    __half2* p = (__half2*)(qkv + base);
    float2 v = __half22float2(*p);
    float o0 = v.x * c - v.y * sn;
    float o1 = v.x * sn + v.y * c;
    if (blockIdx.y == 0) { o0 *= QSCALE; o1 *= QSCALE; }
    *p = __floats2half2_rn(o0, o1);
}

// ---------------- flash attention (fp16 MMA, online softmax) ---------------
#define FA_SMEM 98304

__global__ void __launch_bounds__(256, 1) flash_attn(
    const __half* __restrict__ QKV, __half* __restrict__ O) {
    extern __shared__ __align__(1024) char smem[];
    uint32_t sb = smem_u32(smem);
    int tid = threadIdx.x, lane = tid & 31, w = tid >> 5;
    int h = blockIdx.y;
    int qb = gridDim.x - 1 - blockIdx.x;   // heavy tiles first
    int qbase = qb * 128;
    const int LD = 3 * DIM;

    const __half* Qg = QKV + (size_t)qbase * LD + h * HD;
    const __half* Kg = QKV + DIM + h * HD;
    const __half* Vg = QKV + 2 * DIM + h * HD;

#define ISSUE_KV(i, b)                                                        \
    {                                                                         \
        int kv0_ = (i) * 64;                                                  \
        uint32_t kb_ = sb + 32768 + (b) * 32768;                              \
        _Pragma("unroll") for (int it = 0; it < 4; it++) {                    \
            int id = tid + it * 256;                                          \
            int row = id >> 4, ch = id & 15;                                  \
            uint32_t o_ = (uint32_t)(ch >> 3) * 8192 +                        \
                          sw128_(row * 128 + (ch & 7) * 16);                  \
            const __half* ksrc = Kg + (size_t)(kv0_ + row) * LD + ch * 8;     \
            const __half* vsrc = Vg + (size_t)(kv0_ + row) * LD + ch * 8;     \
            CP16(kb_ + o_, ksrc);                                             \
            CP16(kb_ + 16384 + o_, vsrc);                                     \
        }                                                                     \
    }

#pragma unroll
    for (int it = 0; it < 8; it++) {
        int id = tid + it * 256;
        int row = id >> 4, ch = id & 15;
        uint32_t dst = sb + (uint32_t)(ch >> 3) * 16384 +
                       sw128_(row * 128 + (ch & 7) * 16);
        CP16(dst, Qg + (size_t)row * LD + ch * 8);
    }
    ISSUE_KV(0, 0);
    CP_COMMIT();

    float oacc[16][4];
#pragma unroll
    for (int j = 0; j < 16; j++)
#pragma unroll
        for (int t = 0; t < 4; t++) oacc[j][t] = 0.f;
    float m0 = -1e30f, m1 = -1e30f, l0 = 0.f, l1 = 0.f;
    uint32_t qf[8][4];

    int nkb = qb * 2 + 2;
    int sub = lane >> 3;
    int wrow = qbase + w * 16;

    for (int i = 0; i < nkb; i++) {
        int b = i & 1;
        if (i + 1 < nkb) {
            ISSUE_KV(i + 1, b ^ 1);
            CP_COMMIT();
            CP_WAIT(1);
        } else {
            CP_WAIT(0);
        }
        __syncthreads();
        if (i == 0) {
#pragma unroll
            for (int kt = 0; kt < 8; kt++) {
                int r = w * 16 + (lane & 7) + (sub & 1) * 8;
                uint32_t ch = (uint32_t)((kt & 3) * 2 + (sub >> 1));
                uint32_t addr = sb + (uint32_t)(kt >> 2) * 16384 +
                                sw128_(r * 128 + ch * 16);
                LDSM_X4(qf[kt], addr);
            }
        }
        int kv0 = i * 64;
        if (kv0 <= wrow + 15) {
            float sacc[8][4];
#pragma unroll
            for (int j = 0; j < 8; j++)
#pragma unroll
                for (int t = 0; t < 4; t++) sacc[j][t] = 0.f;
            uint32_t Kb = sb + 32768 + b * 32768;
#pragma unroll
            for (int ng = 0; ng < 4; ng++) {
                int nr = ng * 16 + (sub >> 1) * 8 + (lane & 7);
#pragma unroll
                for (int kt = 0; kt < 8; kt++) {
                    uint32_t bb[4];
                    uint32_t ch = (uint32_t)((kt & 3) * 2 + (sub & 1));
                    uint32_t addr = Kb + (uint32_t)(kt >> 2) * 8192 +
                                    sw128_(nr * 128 + ch * 16);
                    LDSM_X4(bb, addr);
                    MMA_FP16(sacc[ng * 2], qf[kt], bb[0], bb[1]);
                    MMA_FP16(sacc[ng * 2 + 1], qf[kt], bb[2], bb[3]);
                }
            }
            int r0 = wrow + (lane >> 2), r1 = r0 + 8;
            if (kv0 + 63 > r0) {
#pragma unroll
                for (int j = 0; j < 8; j++) {
                    int c = kv0 + j * 8 + 2 * (lane & 3);
                    if (c > r0) sacc[j][0] = -1e30f;
                    if (c + 1 > r0) sacc[j][1] = -1e30f;
                    if (c > r1) sacc[j][2] = -1e30f;
                    if (c + 1 > r1) sacc[j][3] = -1e30f;
                }
            }
            float mx0 = -1e30f, mx1 = -1e30f;
#pragma unroll
            for (int j = 0; j < 8; j++) {
                mx0 = fmaxf(mx0, fmaxf(sacc[j][0], sacc[j][1]));
                mx1 = fmaxf(mx1, fmaxf(sacc[j][2], sacc[j][3]));
            }
            mx0 = fmaxf(mx0, __shfl_xor_sync(~0u, mx0, 1));
            mx0 = fmaxf(mx0, __shfl_xor_sync(~0u, mx0, 2));
            mx1 = fmaxf(mx1, __shfl_xor_sync(~0u, mx1, 1));
            mx1 = fmaxf(mx1, __shfl_xor_sync(~0u, mx1, 2));
            float m0n = fmaxf(m0, mx0), m1n = fmaxf(m1, mx1);
            float c0 = exp2f(m0 - m0n), c1 = exp2f(m1 - m1n);
            float rs0 = 0.f, rs1 = 0.f;
#pragma unroll
            for (int j = 0; j < 8; j++) {
                sacc[j][0] = exp2f(sacc[j][0] - m0n);
                sacc[j][1] = exp2f(sacc[j][1] - m0n);
                sacc[j][2] = exp2f(sacc[j][2] - m1n);
                sacc[j][3] = exp2f(sacc[j][3] - m1n);
                rs0 += sacc[j][0] + sacc[j][1];
                rs1 += sacc[j][2] + sacc[j][3];
            }
            rs0 += __shfl_xor_sync(~0u, rs0, 1);
            rs0 += __shfl_xor_sync(~0u, rs0, 2);
            rs1 += __shfl_xor_sync(~0u, rs1, 1);
            rs1 += __shfl_xor_sync(~0u, rs1, 2);
            l0 = l0 * c0 + rs0;
            l1 = l1 * c1 + rs1;
            m0 = m0n;
            m1 = m1n;
#pragma unroll
            for (int j = 0; j < 16; j++) {
                oacc[j][0] *= c0; oacc[j][1] *= c0;
                oacc[j][2] *= c1; oacc[j][3] *= c1;
            }
            uint32_t Vb = Kb + 16384;
#pragma unroll
            for (int kt = 0; kt < 4; kt++) {
                uint32_t a[4];
                a[0] = cvt2h(sacc[2 * kt][0], sacc[2 * kt][1]);
                a[1] = cvt2h(sacc[2 * kt][2], sacc[2 * kt][3]);
                a[2] = cvt2h(sacc[2 * kt + 1][0], sacc[2 * kt + 1][1]);
                a[3] = cvt2h(sacc[2 * kt + 1][2], sacc[2 * kt + 1][3]);
                int kr = kt * 16 + (lane & 7) + ((lane >> 3) & 1) * 8;
#pragma unroll
                for (int dp = 0; dp < 8; dp++) {
                    int dim = dp * 16 + ((lane >> 4) & 1) * 8;
                    uint32_t addr = Vb + (uint32_t)(dim >> 6) * 8192 +
                                    sw128_(kr * 128 + ((dim & 63) >> 3) * 16);
                    uint32_t vv[4];
                    LDSM_X4_T(vv, addr);
                    MMA_FP16(oacc[dp * 2], a, vv[0], vv[1]);
                    MMA_FP16(oacc[dp * 2 + 1], a, vv[2], vv[3]);
                }
            }
        }
        __syncthreads();
    }

    float i0 = 1.f / l0, i1 = 1.f / l1;
    int r0g = qbase + w * 16 + (lane >> 2);
#pragma unroll
    for (int j = 0; j < 16; j++) {
        int col = h * HD + j * 8 + 2 * (lane & 3);
        *(uint32_t*)(O + (size_t)r0g * DIM + col) =
            cvt2h(oacc[j][0] * i0, oacc[j][1] * i0);
        *(uint32_t*)(O + (size_t)(r0g + 8) * DIM + col) =
            cvt2h(oacc[j][2] * i1, oacc[j][3] * i1);
    }
#undef ISSUE_KV
}

// ---------------- launch ----------------
extern "C" void kernel_launch(void* const* d_in, const int* in_sizes, int n_in,
                              void* d_out, int out_size) {
    const float* x   = (const float*)d_in[0];
    const float* fc  = (const float*)d_in[1];
    const float* fs  = (const float*)d_in[2];
    const float* anw = (const float*)d_in[4];
    const float* wq  = (const float*)d_in[5];
    const float* wk  = (const float*)d_in[6];
    const float* wv  = (const float*)d_in[7];
    const float* wo  = (const float*)d_in[8];
    const float* fnw = (const float*)d_in[9];
    const float* w1  = (const float*)d_in[10];
    const float* w2  = (const float*)d_in[11];
    const float* w3  = (const float*)d_in[12];
    float* out = (float*)d_out;

    float* h;
    __half *xnh, *qkvh, *ath, *gh;
    __half *wqkvh, *woh, *w13h, *w2h;
    cudaGetSymbolAddress((void**)&h,     g_h);
    cudaGetSymbolAddress((void**)&xnh,   g_xnh);
    cudaGetSymbolAddress((void**)&qkvh,  g_qkvh);
    cudaGetSymbolAddress((void**)&ath,   g_ath);
    cudaGetSymbolAddress((void**)&gh,    g_gh);
    cudaGetSymbolAddress((void**)&wqkvh, g_wqkvh);
    cudaGetSymbolAddress((void**)&woh,   g_woh);
    cudaGetSymbolAddress((void**)&w13h,  g_w13h);
    cudaGetSymbolAddress((void**)&w2h,   g_w2h);

    cudaFuncSetAttribute(gemm_p<0>, cudaFuncAttributeMaxDynamicSharedMemorySize, GEMM_SMEM);
    cudaFuncSetAttribute(gemm_p<1>, cudaFuncAttributeMaxDynamicSharedMemorySize, GEMM_SMEM);
    cudaFuncSetAttribute(gemm_p<2>, cudaFuncAttributeMaxDynamicSharedMemorySize, GEMM_SMEM);
    cudaFuncSetAttribute(flash_attn, cudaFuncAttributeMaxDynamicSharedMemorySize, FA_SMEM);

    const int ndd4 = DIM * DIM / 4;
    const int nhd4 = HID * DIM / 4;
    convert_kernel<<<(ndd4 + 255) / 256, 256>>>(wq, wqkvh, ndd4);
    convert_kernel<<<(ndd4 + 255) / 256, 256>>>(wk, wqkvh + (size_t)DIM * DIM, ndd4);
    convert_kernel<<<(ndd4 + 255) / 256, 256>>>(wv, wqkvh + (size_t)2 * DIM * DIM, ndd4);
    convert_kernel<<<(ndd4 + 255) / 256, 256>>>(wo, woh, ndd4);
    convert_w13<<<(nhd4 + 255) / 256, 256>>>(w1, w3, w13h, nhd4);
    convert_kernel<<<(nhd4 + 255) / 256, 256>>>(w2, w2h, nhd4);

    // 1. xn = rmsnorm(x)
    rmsnorm_h<<<SEQ, 256>>>(x, anw, xnh);
    // 2. qkv = xn @ [wq;wk;wv]^T (fp16 out)
    gemm_p<1><<<GEMM_GRID, 256, GEMM_SMEM>>>(xnh, wqkvh, nullptr, qkvh, SEQ, 3 * DIM, DIM);
    // 3. rope
    rotary_h<<<dim3(SEQ * NH * 64 / 256, 2), 256>>>(qkvh, fc, fs);
    // 4. flash attention
    flash_attn<<<dim3(SEQ / 128, NH), 256, FA_SMEM>>>(qkvh, ath);
    // 5. h = x + attn @ wo^T
    gemm_p<0><<<GEMM_GRID, 256, GEMM_SMEM>>>(ath, woh, x, h, SEQ, DIM, DIM);
    // 6. hn = rmsnorm(h)
    rmsnorm_h<<<SEQ, 256>>>(h, fnw, xnh);
    // 7+8. g = silu(hn@w1^T) * (hn@w3^T)   (fused swiglu epilogue)
    gemm_p<2><<<GEMM_GRID, 256, GEMM_SMEM>>>(xnh, w13h, nullptr, gh, SEQ, 2 * HID, DIM);
    // 9. out = h + g @ w2^T
    gemm_p<0><<<GEMM_GRID, 256, GEMM_SMEM>>>(gh, w2h, h, out, SEQ, DIM, HID);
}